// round 4
// baseline (speedup 1.0000x reference)
#include <cuda_runtime.h>
#include <math.h>

#define N_NODES 30000
#define N_EDGES 100000
#define EP      (N_EDGES + N_NODES)   // edges + self loops = 130000
#define N_GRAPH 1024
#define HEADS1  10
#define DCH     128
#define F1      1280                  // HEADS1 * DCH
#define FXD     78
#define FXT     954

// ---------------- scratch (device globals; no allocations allowed) ----------
__device__ float g_h1  [(size_t)N_NODES * F1];
__device__ float g_acc1[(size_t)N_NODES * F1];
__device__ float g_h2  [N_NODES * DCH];
__device__ float g_acc2[N_NODES * DCH];
__device__ float g_as  [N_NODES * HEADS1];
__device__ float g_ad  [N_NODES * HEADS1];
__device__ float g_emax[N_NODES * HEADS1];
__device__ float g_den [N_NODES * HEADS1];
__device__ float g_edge[EP * HEADS1];
__device__ float g_pool[N_GRAPH * DCH];
__device__ float g_cn  [N_GRAPH * FXT];
__device__ float g_c1  [N_GRAPH * 2048];
__device__ float g_c2  [N_GRAPH * 512];
__device__ float g_xc  [N_GRAPH * 512];
__device__ float g_f1  [N_GRAPH * 1024];
__device__ float g_f2  [N_GRAPH * 512];
__device__ float g_f3  [N_GRAPH * 128];

// ---------------- helpers ----------------
__device__ __forceinline__ void atomicMaxF(float* a, float v) {
    if (v >= 0.f) atomicMax((int*)a, __float_as_int(v));
    else          atomicMin((unsigned int*)a, __float_as_uint(v));
}

__device__ __forceinline__ void redAdd4(float* p, float4 v) {
    asm volatile("red.global.add.v4.f32 [%0], {%1,%2,%3,%4};"
                 :: "l"(p), "f"(v.x), "f"(v.y), "f"(v.z), "f"(v.w) : "memory");
}

// ---------------- generic tiled GEMM: C = act(A[M,K] @ B[K,N] + bias) -------
// act: 0 = none, 1 = relu.  B is row-major [K,N] (ldb = N), C has ldc stride.
__global__ void gemm_k(const float* __restrict__ A, const float* __restrict__ B,
                       const float* __restrict__ bias, float* __restrict__ C,
                       int M, int N, int K, int ldc, int act)
{
    __shared__ float As[16][68];   // padded to dodge bank conflicts
    __shared__ float Bs[16][64];
    int tid = threadIdx.x;
    int tx = tid & 15, ty = tid >> 4;
    int m0 = blockIdx.y * 64, n0 = blockIdx.x * 64;
    float acc[4][4] = {};

    for (int k0 = 0; k0 < K; k0 += 16) {
        #pragma unroll
        for (int it = 0; it < 4; it++) {
            int id = tid + it * 256;
            int r = id >> 4, c = id & 15;
            int m = m0 + r, k = k0 + c;
            As[c][r] = (m < M && k < K) ? A[(size_t)m * K + k] : 0.f;
        }
        #pragma unroll
        for (int it = 0; it < 4; it++) {
            int id = tid + it * 256;
            int r = id >> 6, c = id & 63;
            int k = k0 + r, n = n0 + c;
            Bs[r][c] = (k < K && n < N) ? B[(size_t)k * N + n] : 0.f;
        }
        __syncthreads();
        #pragma unroll
        for (int k = 0; k < 16; k++) {
            float4 a4 = *(const float4*)&As[k][ty * 4];
            float4 b4 = *(const float4*)&Bs[k][tx * 4];
            float av[4] = {a4.x, a4.y, a4.z, a4.w};
            float bv[4] = {b4.x, b4.y, b4.z, b4.w};
            #pragma unroll
            for (int i = 0; i < 4; i++)
                #pragma unroll
                for (int j = 0; j < 4; j++)
                    acc[i][j] += av[i] * bv[j];
        }
        __syncthreads();
    }
    #pragma unroll
    for (int i = 0; i < 4; i++) {
        int m = m0 + ty * 4 + i;
        if (m >= M) break;
        #pragma unroll
        for (int j = 0; j < 4; j++) {
            int n = n0 + tx * 4 + j;
            if (n >= N) continue;
            float v = acc[i][j];
            if (bias) v += bias[n];
            if (act == 1) v = fmaxf(v, 0.f);
            C[(size_t)m * ldc + n] = v;
        }
    }
}

// ---------------- elementwise fills ----------------
__global__ void fill_k(float* __restrict__ p, float v, int n) {
    int t = blockIdx.x * blockDim.x + threadIdx.x;
    if (t < n) p[t] = v;
}

// alpha_s / alpha_d per (node, head): dot of h row-chunk with attention vector
__global__ void alpha_k(const float* __restrict__ h,
                        const float* __restrict__ a_s, const float* __restrict__ a_d,
                        float* __restrict__ os, float* __restrict__ od,
                        int n, int heads)
{
    int t = blockIdx.x * blockDim.x + threadIdx.x;
    if (t >= n * heads) return;
    int hd = t % heads;
    const float* hp = h + (size_t)t * DCH;
    const float* sp = a_s + hd * DCH;
    const float* dp = a_d + hd * DCH;
    float s1 = 0.f, s2 = 0.f;
    #pragma unroll 8
    for (int c = 0; c < DCH; c += 4) {
        float4 hv = *(const float4*)(hp + c);
        float4 sv = *(const float4*)(sp + c);
        float4 dv = *(const float4*)(dp + c);
        s1 += hv.x * sv.x + hv.y * sv.y + hv.z * sv.z + hv.w * sv.w;
        s2 += hv.x * dv.x + hv.y * dv.y + hv.z * dv.z + hv.w * dv.w;
    }
    os[t] = s1;
    od[t] = s2;
}

__device__ __forceinline__ void edge_ends(int e, const int* __restrict__ ei,
                                          int& src, int& dst)
{
    if (e < N_EDGES) { src = ei[e]; dst = ei[N_EDGES + e]; }
    else             { src = dst = e - N_EDGES; }
}

__global__ void edge_max_k(const int* __restrict__ ei,
                           const float* __restrict__ as, const float* __restrict__ ad,
                           float* __restrict__ emax, float* __restrict__ ebuf, int heads)
{
    int t = blockIdx.x * blockDim.x + threadIdx.x;
    if (t >= EP * heads) return;
    int e = t / heads, hd = t - e * heads;
    int src, dst; edge_ends(e, ei, src, dst);
    float v = as[src * heads + hd] + ad[dst * heads + hd];
    v = v > 0.f ? v : 0.2f * v;           // leaky_relu 0.2
    ebuf[t] = v;
    atomicMaxF(&emax[dst * heads + hd], v);
}

__global__ void edge_exp_k(const int* __restrict__ ei,
                           const float* __restrict__ emax, float* __restrict__ den,
                           float* __restrict__ ebuf, int heads)
{
    int t = blockIdx.x * blockDim.x + threadIdx.x;
    if (t >= EP * heads) return;
    int e = t / heads, hd = t - e * heads;
    int src, dst; edge_ends(e, ei, src, dst);
    (void)src;
    float ex = expf(ebuf[t] - emax[dst * heads + hd]);
    ebuf[t] = ex;
    atomicAdd(&den[dst * heads + hd], ex);
}

// one warp per (edge, head); lane covers 4 channels
__global__ void edge_aggr_k(const int* __restrict__ ei,
                            const float* __restrict__ ebuf, const float* __restrict__ den,
                            const float* __restrict__ h, float* __restrict__ acc, int heads)
{
    int w = (blockIdx.x * blockDim.x + threadIdx.x) >> 5;
    int lane = threadIdx.x & 31;
    if (w >= EP * heads) return;
    int e = w / heads, hd = w - e * heads;
    int src, dst; edge_ends(e, ei, src, dst);
    float alpha = ebuf[w] / (den[dst * heads + hd] + 1e-16f);
    const float4 v = *(const float4*)(h + ((size_t)src * heads + hd) * DCH + lane * 4);
    float4 m = make_float4(v.x * alpha, v.y * alpha, v.z * alpha, v.w * alpha);
    redAdd4(acc + ((size_t)dst * heads + hd) * DCH + lane * 4, m);
}

__global__ void bias_elu_k(float* __restrict__ x, const float* __restrict__ b,
                           int n, int C)
{
    int t = blockIdx.x * blockDim.x + threadIdx.x;
    if (t >= n) return;
    float v = x[t] + b[t % C];
    x[t] = v > 0.f ? v : expm1f(v);
}

__global__ void pool_max_k(const float* __restrict__ h, const int* __restrict__ batch,
                           float* __restrict__ pool)
{
    int t = blockIdx.x * blockDim.x + threadIdx.x;
    if (t >= N_NODES * DCH) return;
    int nidx = t >> 7, c = t & 127;
    atomicMaxF(&pool[batch[nidx] * DCH + c], h[t]);
}

// row-wise L2 normalize (block per row); safe in-place
__global__ void l2norm_k(const float* __restrict__ in, float* __restrict__ out, int cols)
{
    __shared__ float red[256];
    int row = blockIdx.x;
    const float* ip = in + (size_t)row * cols;
    float s = 0.f;
    for (int c = threadIdx.x; c < cols; c += 256) { float v = ip[c]; s += v * v; }
    red[threadIdx.x] = s;
    __syncthreads();
    for (int off = 128; off > 0; off >>= 1) {
        if (threadIdx.x < off) red[threadIdx.x] += red[threadIdx.x + off];
        __syncthreads();
    }
    float sc = 1.f / fmaxf(sqrtf(red[0]), 1e-12f);
    float* op = out + (size_t)row * cols;
    for (int c = threadIdx.x; c < cols; c += 256) op[c] = ip[c] * sc;
}

// ---------------- host orchestration ----------------
static void gemm(const float* A, const float* B, const float* bias, float* C,
                 int M, int N, int K, int ldc, int act)
{
    dim3 grid((N + 63) / 64, (M + 63) / 64);
    gemm_k<<<grid, 256>>>(A, B, bias, C, M, N, K, ldc, act);
}

static void run_branch(const float* x, const int* ei, const int* batch,
                       const float* W1, const float* a_s1, const float* a_d1, const float* b1,
                       const float* W2, const float* a_s2, const float* a_d2, const float* b2,
                       const float* Wg, const float* bg,
                       float* h1, float* acc1, float* h2, float* acc2,
                       float* as, float* ad, float* emax, float* den, float* ebuf,
                       float* pool, float* vout)
{
    const int T = 256;
    // --- GATConv1 (H=10, D=128) ---
    gemm(x, W1, nullptr, h1, N_NODES, F1, FXD, F1, 0);
    alpha_k<<<(N_NODES * HEADS1 + T - 1) / T, T>>>(h1, a_s1, a_d1, as, ad, N_NODES, HEADS1);
    fill_k<<<(N_NODES * HEADS1 + T - 1) / T, T>>>(emax, -INFINITY, N_NODES * HEADS1);
    fill_k<<<(N_NODES * HEADS1 + T - 1) / T, T>>>(den, 0.f, N_NODES * HEADS1);
    fill_k<<<(N_NODES * F1 + T - 1) / T, T>>>(acc1, 0.f, N_NODES * F1);
    edge_max_k<<<(EP * HEADS1 + T - 1) / T, T>>>(ei, as, ad, emax, ebuf, HEADS1);
    edge_exp_k<<<(EP * HEADS1 + T - 1) / T, T>>>(ei, emax, den, ebuf, HEADS1);
    edge_aggr_k<<<((size_t)EP * HEADS1 * 32 + T - 1) / T, T>>>(ei, ebuf, den, h1, acc1, HEADS1);
    bias_elu_k<<<(N_NODES * F1 + T - 1) / T, T>>>(acc1, b1, N_NODES * F1, F1);

    // --- GATConv2 (H=1, D=128) ---
    gemm(acc1, W2, nullptr, h2, N_NODES, DCH, F1, DCH, 0);
    alpha_k<<<(N_NODES + T - 1) / T, T>>>(h2, a_s2, a_d2, as, ad, N_NODES, 1);
    fill_k<<<(N_NODES + T - 1) / T, T>>>(emax, -INFINITY, N_NODES);
    fill_k<<<(N_NODES + T - 1) / T, T>>>(den, 0.f, N_NODES);
    fill_k<<<(N_NODES * DCH + T - 1) / T, T>>>(acc2, 0.f, N_NODES * DCH);
    edge_max_k<<<(EP + T - 1) / T, T>>>(ei, as, ad, emax, ebuf, 1);
    edge_exp_k<<<(EP + T - 1) / T, T>>>(ei, emax, den, ebuf, 1);
    edge_aggr_k<<<((size_t)EP * 32 + T - 1) / T, T>>>(ei, ebuf, den, h2, acc2, 1);
    bias_elu_k<<<(N_NODES * DCH + T - 1) / T, T>>>(acc2, b2, N_NODES * DCH, DCH);

    // --- global max pool + Wg ---
    fill_k<<<(N_GRAPH * DCH + T - 1) / T, T>>>(pool, -INFINITY, N_GRAPH * DCH);
    pool_max_k<<<(N_NODES * DCH + T - 1) / T, T>>>(acc2, batch, pool);
    gemm(pool, Wg, bg, vout, N_GRAPH, DCH, DCH, 512, 1);   // relu, strided into concat buf
}

extern "C" void kernel_launch(void* const* d_in, const int* in_sizes, int n_in,
                              void* d_out, int out_size)
{
    const float* x1   = (const float*)d_in[0];
    const int*   ei1  = (const int*)  d_in[1];
    const int*   bt1  = (const int*)  d_in[2];
    const float* x2   = (const float*)d_in[3];
    const int*   ei2  = (const int*)  d_in[4];
    const int*   bt2  = (const int*)  d_in[5];
    const float* cell = (const float*)d_in[6];
    const float* W1   = (const float*)d_in[7];
    const float* aS1  = (const float*)d_in[8];
    const float* aD1  = (const float*)d_in[9];
    const float* b1   = (const float*)d_in[10];
    const float* W2   = (const float*)d_in[11];
    const float* aS2  = (const float*)d_in[12];
    const float* aD2  = (const float*)d_in[13];
    const float* b2   = (const float*)d_in[14];
    const float* Wg   = (const float*)d_in[15];
    const float* bg   = (const float*)d_in[16];
    const float* Wr1  = (const float*)d_in[17];
    const float* br1  = (const float*)d_in[18];
    const float* Wr2  = (const float*)d_in[19];
    const float* br2  = (const float*)d_in[20];
    const float* Wr3  = (const float*)d_in[21];
    const float* br3  = (const float*)d_in[22];
    const float* Wf1  = (const float*)d_in[23];
    const float* bf1  = (const float*)d_in[24];
    const float* Wf2  = (const float*)d_in[25];
    const float* bf2  = (const float*)d_in[26];
    const float* Wf3  = (const float*)d_in[27];
    const float* bf3  = (const float*)d_in[28];
    const float* Wo   = (const float*)d_in[29];
    const float* bo   = (const float*)d_in[30];
    float* out = (float*)d_out;

    float *h1, *acc1, *h2, *acc2, *as, *ad, *emax, *den, *ebuf, *pool;
    float *cn, *c1, *c2, *xc, *f1, *f2, *f3;
    cudaGetSymbolAddress((void**)&h1,   g_h1);
    cudaGetSymbolAddress((void**)&acc1, g_acc1);
    cudaGetSymbolAddress((void**)&h2,   g_h2);
    cudaGetSymbolAddress((void**)&acc2, g_acc2);
    cudaGetSymbolAddress((void**)&as,   g_as);
    cudaGetSymbolAddress((void**)&ad,   g_ad);
    cudaGetSymbolAddress((void**)&emax, g_emax);
    cudaGetSymbolAddress((void**)&den,  g_den);
    cudaGetSymbolAddress((void**)&ebuf, g_edge);
    cudaGetSymbolAddress((void**)&pool, g_pool);
    cudaGetSymbolAddress((void**)&cn,   g_cn);
    cudaGetSymbolAddress((void**)&c1,   g_c1);
    cudaGetSymbolAddress((void**)&c2,   g_c2);
    cudaGetSymbolAddress((void**)&xc,   g_xc);
    cudaGetSymbolAddress((void**)&f1,   g_f1);
    cudaGetSymbolAddress((void**)&f2,   g_f2);
    cudaGetSymbolAddress((void**)&f3,   g_f3);

    // two GNN branches -> xc[:, 0:128) and xc[:, 128:256)
    run_branch(x1, ei1, bt1, W1, aS1, aD1, b1, W2, aS2, aD2, b2, Wg, bg,
               h1, acc1, h2, acc2, as, ad, emax, den, ebuf, pool, xc);
    run_branch(x2, ei2, bt2, W1, aS1, aD1, b1, W2, aS2, aD2, b2, Wg, bg,
               h1, acc1, h2, acc2, as, ad, emax, den, ebuf, pool, xc + 128);

    // cell branch -> xc[:, 256:512)
    l2norm_k<<<N_GRAPH, 256>>>(cell, cn, FXT);
    gemm(cn, Wr1, br1, c1, N_GRAPH, 2048, FXT, 2048, 1);
    gemm(c1, Wr2, br2, c2, N_GRAPH, 512, 2048, 512, 1);
    gemm(c2, Wr3, br3, xc + 256, N_GRAPH, 256, 512, 512, 1);

    // fuse head
    l2norm_k<<<N_GRAPH, 256>>>(xc, xc, 512);
    gemm(xc, Wf1, bf1, f1, N_GRAPH, 1024, 512, 1024, 1);
    gemm(f1, Wf2, bf2, f2, N_GRAPH, 512, 1024, 512, 1);
    gemm(f2, Wf3, bf3, f3, N_GRAPH, 128, 512, 128, 1);
    gemm(f3, Wo, bo, out, N_GRAPH, 2, 128, 2, 0);
}

// round 6
// speedup vs baseline: 1.2726x; 1.2726x over previous
#include <cuda_runtime.h>
#include <math.h>

#define N_NODES 30000
#define N_EDGES 100000
#define EP      (N_EDGES + N_NODES)   // edges + self loops = 130000
#define N_GRAPH 1024
#define HEADS1  10
#define DCH     128
#define F1      1280                  // HEADS1 * DCH
#define FXD     78
#define FXT     954

// ---------------- scratch (device globals; no allocations allowed) ----------
__device__ float g_h1  [(size_t)N_NODES * F1];
__device__ float g_acc1[(size_t)N_NODES * F1];
__device__ float g_h2  [N_NODES * DCH];
__device__ float g_acc2[N_NODES * DCH];
__device__ float g_as  [N_NODES * HEADS1];
__device__ float g_ad  [N_NODES * HEADS1];
__device__ float g_emax[N_NODES * HEADS1];
__device__ float g_den [N_NODES * HEADS1];
__device__ float g_edge[EP * HEADS1];
__device__ float g_pool[N_GRAPH * DCH];
__device__ float g_cn  [N_GRAPH * FXT];
__device__ float g_c1  [N_GRAPH * 2048];
__device__ float g_c2  [N_GRAPH * 512];
__device__ float g_xc  [N_GRAPH * 512];
__device__ float g_f1  [N_GRAPH * 1024];
__device__ float g_f2  [N_GRAPH * 512];
__device__ float g_f3  [N_GRAPH * 128];

// ---------------- helpers ----------------
__device__ __forceinline__ void atomicMaxF(float* a, float v) {
    if (v >= 0.f) atomicMax((int*)a, __float_as_int(v));
    else          atomicMin((unsigned int*)a, __float_as_uint(v));
}

__device__ __forceinline__ void redAdd4(float* p, float4 v) {
    asm volatile("red.global.add.v4.f32 [%0], {%1,%2,%3,%4};"
                 :: "l"(p), "f"(v.x), "f"(v.y), "f"(v.z), "f"(v.w) : "memory");
}

// ---- packed fp32x2 (Blackwell FFMA2 pipe) ----
__device__ __forceinline__ unsigned long long pk2(float x, float y) {
    unsigned long long r;
    asm("mov.b64 %0, {%1, %2};" : "=l"(r) : "f"(x), "f"(y));
    return r;
}
__device__ __forceinline__ void fma2(unsigned long long& d,
                                     unsigned long long a, unsigned long long b) {
    asm("fma.rn.f32x2 %0, %1, %2, %0;" : "+l"(d) : "l"(a), "l"(b));
}
__device__ __forceinline__ float2 upk2(unsigned long long v) {
    float2 r;
    asm("mov.b64 {%0, %1}, %2;" : "=f"(r.x), "=f"(r.y) : "l"(v));
    return r;
}

// ---------------- SGEMM v2: 128x128 tile, 8x8 microtile, FFMA2 inner -------
// C = act(A[M,K] @ B[K,N] + bias), B row-major [K,N], C stride ldc.
#define TM 128
#define TN 128
#define TK 16

__global__ __launch_bounds__(256)
void gemm_k(const float* __restrict__ A, const float* __restrict__ B,
            const float* __restrict__ bias, float* __restrict__ C,
            int M, int N, int K, int ldc, int act)
{
    __shared__ float As[TK][TM + 4];
    __shared__ float Bs[TK][TN];

    int tid = threadIdx.x;
    int tx = tid & 15, ty = tid >> 4;
    int m0 = blockIdx.y * TM, n0 = blockIdx.x * TN;

    // staging coordinates
    int ar = tid >> 1;            // 0..127  (A tile row)
    int ac0 = (tid & 1) * 8;      // 0 or 8  (A tile col base)
    int br = tid >> 5;            // 0..7    (B tile row, +8 second pass)
    int bc = (tid & 31) * 4;      // 0..124  (B tile col base)

    float a_reg[8];
    float4 b_reg[2];
    const bool k_vec = ((K & 3) == 0);

    auto loadA = [&](int k0) {
        int gm = m0 + ar;
        if (gm < M) {
            const float* ap = A + (size_t)gm * K + k0 + ac0;
            if (k_vec && k0 + ac0 + 7 < K) {
                float4 v0 = *(const float4*)(ap);
                float4 v1 = *(const float4*)(ap + 4);
                a_reg[0] = v0.x; a_reg[1] = v0.y; a_reg[2] = v0.z; a_reg[3] = v0.w;
                a_reg[4] = v1.x; a_reg[5] = v1.y; a_reg[6] = v1.z; a_reg[7] = v1.w;
            } else {
                #pragma unroll
                for (int j = 0; j < 8; j++) {
                    int gk = k0 + ac0 + j;
                    a_reg[j] = (gk < K) ? ap[j] : 0.f;
                }
            }
        } else {
            #pragma unroll
            for (int j = 0; j < 8; j++) a_reg[j] = 0.f;
        }
    };
    auto loadB = [&](int k0) {
        #pragma unroll
        for (int it = 0; it < 2; it++) {
            int gk = k0 + br + it * 8;
            int gn = n0 + bc;
            float4 v = make_float4(0.f, 0.f, 0.f, 0.f);
            if (gk < K) {
                const float* bp = B + (size_t)gk * N + gn;
                if (gn + 3 < N) v = *(const float4*)bp;
                else {
                    if (gn     < N) v.x = bp[0];
                    if (gn + 1 < N) v.y = bp[1];
                    if (gn + 2 < N) v.z = bp[2];
                }
            }
            b_reg[it] = v;
        }
    };
    auto storeA = [&]() {
        #pragma unroll
        for (int j = 0; j < 8; j++) As[ac0 + j][ar] = a_reg[j];
    };
    auto storeB = [&]() {
        *(float4*)&Bs[br][bc]     = b_reg[0];
        *(float4*)&Bs[br + 8][bc] = b_reg[1];
    };

    unsigned long long acc[8][4] = {};  // 8 m-values x 4 n-pairs (bits 0 == {0.f,0.f})

    int nk = (K + TK - 1) / TK;
    loadA(0); loadB(0);
    storeA(); storeB();
    __syncthreads();

    for (int t = 1; t <= nk; t++) {
        if (t < nk) { loadA(t * TK); loadB(t * TK); }
        #pragma unroll
        for (int k = 0; k < TK; k++) {
            float4 aL = *(const float4*)&As[k][ty * 4];
            float4 aH = *(const float4*)&As[k][64 + ty * 4];
            float4 bL = *(const float4*)&Bs[k][tx * 4];
            float4 bH = *(const float4*)&Bs[k][64 + tx * 4];
            unsigned long long bp[4] = { pk2(bL.x, bL.y), pk2(bL.z, bL.w),
                                         pk2(bH.x, bH.y), pk2(bH.z, bH.w) };
            float as8[8] = { aL.x, aL.y, aL.z, aL.w, aH.x, aH.y, aH.z, aH.w };
            #pragma unroll
            for (int i = 0; i < 8; i++) {
                unsigned long long ap = pk2(as8[i], as8[i]);
                #pragma unroll
                for (int p = 0; p < 4; p++) fma2(acc[i][p], ap, bp[p]);
            }
        }
        __syncthreads();
        if (t < nk) { storeA(); storeB(); __syncthreads(); }
    }

    // epilogue
    #pragma unroll
    for (int i = 0; i < 8; i++) {
        int m = m0 + ((i < 4) ? (ty * 4 + i) : (64 + ty * 4 + (i - 4)));
        if (m >= M) continue;
        #pragma unroll
        for (int p = 0; p < 4; p++) {
            int n = n0 + ((p < 2) ? 0 : 64) + tx * 4 + (p & 1) * 2;
            float2 v = upk2(acc[i][p]);
            float vx = v.x, vy = v.y;
            if (bias) { if (n < N) vx += bias[n]; if (n + 1 < N) vy += bias[n + 1]; }
            if (act == 1) { vx = fmaxf(vx, 0.f); vy = fmaxf(vy, 0.f); }
            if (n     < N) C[(size_t)m * ldc + n]     = vx;
            if (n + 1 < N) C[(size_t)m * ldc + n + 1] = vy;
        }
    }
}

// ---------------- elementwise ----------------
__global__ void fill4_k(float4* __restrict__ p, float v, int n4) {
    int t = blockIdx.x * blockDim.x + threadIdx.x;
    if (t < n4) p[t] = make_float4(v, v, v, v);
}

// alpha_s / alpha_d per (node, head)
__global__ void alpha_k(const float* __restrict__ h,
                        const float* __restrict__ a_s, const float* __restrict__ a_d,
                        float* __restrict__ os, float* __restrict__ od,
                        int n, int heads)
{
    int t = blockIdx.x * blockDim.x + threadIdx.x;
    if (t >= n * heads) return;
    int hd = t % heads;
    const float* hp = h + (size_t)t * DCH;
    const float* sp = a_s + hd * DCH;
    const float* dp = a_d + hd * DCH;
    float s1 = 0.f, s2 = 0.f;
    #pragma unroll 8
    for (int c = 0; c < DCH; c += 4) {
        float4 hv = *(const float4*)(hp + c);
        float4 sv = *(const float4*)(sp + c);
        float4 dv = *(const float4*)(dp + c);
        s1 += hv.x * sv.x + hv.y * sv.y + hv.z * sv.z + hv.w * sv.w;
        s2 += hv.x * dv.x + hv.y * dv.y + hv.z * dv.z + hv.w * dv.w;
    }
    os[t] = s1;
    od[t] = s2;
}

__device__ __forceinline__ void edge_ends(int e, const int* __restrict__ ei,
                                          int& src, int& dst)
{
    if (e < N_EDGES) { src = ei[e]; dst = ei[N_EDGES + e]; }
    else             { src = dst = e - N_EDGES; }
}

__global__ void edge_max_k(const int* __restrict__ ei,
                           const float* __restrict__ as, const float* __restrict__ ad,
                           float* __restrict__ emax, float* __restrict__ ebuf, int heads)
{
    int t = blockIdx.x * blockDim.x + threadIdx.x;
    if (t >= EP * heads) return;
    int e = t / heads, hd = t - e * heads;
    int src, dst; edge_ends(e, ei, src, dst);
    float v = as[src * heads + hd] + ad[dst * heads + hd];
    v = v > 0.f ? v : 0.2f * v;           // leaky_relu 0.2
    ebuf[t] = v;
    atomicMaxF(&emax[dst * heads + hd], v);
}

__global__ void edge_exp_k(const int* __restrict__ ei,
                           const float* __restrict__ emax, float* __restrict__ den,
                           float* __restrict__ ebuf, int heads)
{
    int t = blockIdx.x * blockDim.x + threadIdx.x;
    if (t >= EP * heads) return;
    int e = t / heads, hd = t - e * heads;
    int src, dst; edge_ends(e, ei, src, dst);
    (void)src;
    float ex = __expf(ebuf[t] - emax[dst * heads + hd]);
    ebuf[t] = ex;
    atomicAdd(&den[dst * heads + hd], ex);
}

// one warp per (edge, head); lane covers 4 channels
__global__ void edge_aggr_k(const int* __restrict__ ei,
                            const float* __restrict__ ebuf, const float* __restrict__ den,
                            const float* __restrict__ h, float* __restrict__ acc, int heads)
{
    int w = (blockIdx.x * blockDim.x + threadIdx.x) >> 5;
    int lane = threadIdx.x & 31;
    if (w >= EP * heads) return;
    int e = w / heads, hd = w - e * heads;
    int src, dst; edge_ends(e, ei, src, dst);
    float alpha = ebuf[w] / (den[dst * heads + hd] + 1e-16f);
    const float4 v = *(const float4*)(h + ((size_t)src * heads + hd) * DCH + lane * 4);
    float4 m = make_float4(v.x * alpha, v.y * alpha, v.z * alpha, v.w * alpha);
    redAdd4(acc + ((size_t)dst * heads + hd) * DCH + lane * 4, m);
}

__global__ void bias_elu4_k(float4* __restrict__ x, const float* __restrict__ b,
                            int n4, int C)
{
    int t = blockIdx.x * blockDim.x + threadIdx.x;
    if (t >= n4) return;
    int c = (t * 4) % C;
    float4 v = x[t];
    const float4 bb = *(const float4*)(b + c);
    v.x += bb.x; v.y += bb.y; v.z += bb.z; v.w += bb.w;
    v.x = v.x > 0.f ? v.x : __expf(v.x) - 1.f;
    v.y = v.y > 0.f ? v.y : __expf(v.y) - 1.f;
    v.z = v.z > 0.f ? v.z : __expf(v.z) - 1.f;
    v.w = v.w > 0.f ? v.w : __expf(v.w) - 1.f;
    x[t] = v;
}

__global__ void pool_max_k(const float* __restrict__ h, const int* __restrict__ batch,
                           float* __restrict__ pool)
{
    int t = blockIdx.x * blockDim.x + threadIdx.x;
    if (t >= N_NODES * DCH) return;
    int nidx = t >> 7, c = t & 127;
    atomicMaxF(&pool[batch[nidx] * DCH + c], h[t]);
}

// row-wise L2 normalize (block per row); safe in-place
__global__ void l2norm_k(const float* __restrict__ in, float* __restrict__ out, int cols)
{
    __shared__ float red[256];
    int row = blockIdx.x;
    const float* ip = in + (size_t)row * cols;
    float s = 0.f;
    for (int c = threadIdx.x; c < cols; c += 256) { float v = ip[c]; s += v * v; }
    red[threadIdx.x] = s;
    __syncthreads();
    for (int off = 128; off > 0; off >>= 1) {
        if (threadIdx.x < off) red[threadIdx.x] += red[threadIdx.x + off];
        __syncthreads();
    }
    float sc = 1.f / fmaxf(sqrtf(red[0]), 1e-12f);
    float* op = out + (size_t)row * cols;
    for (int c = threadIdx.x; c < cols; c += 256) op[c] = ip[c] * sc;
}

// ---------------- host orchestration ----------------
static void gemm(const float* A, const float* B, const float* bias, float* C,
                 int M, int N, int K, int ldc, int act)
{
    dim3 grid((N + TN - 1) / TN, (M + TM - 1) / TM);
    gemm_k<<<grid, 256>>>(A, B, bias, C, M, N, K, ldc, act);
}

static void run_branch(const float* x, const int* ei, const int* batch,
                       const float* W1, const float* a_s1, const float* a_d1, const float* b1,
                       const float* W2, const float* a_s2, const float* a_d2, const float* b2,
                       const float* Wg, const float* bg,
                       float* h1, float* acc1, float* h2, float* acc2,
                       float* as, float* ad, float* emax, float* den, float* ebuf,
                       float* pool, float* vout)
{
    const int T = 256;
    // --- GATConv1 (H=10, D=128) ---
    gemm(x, W1, nullptr, h1, N_NODES, F1, FXD, F1, 0);
    alpha_k<<<(N_NODES * HEADS1 + T - 1) / T, T>>>(h1, a_s1, a_d1, as, ad, N_NODES, HEADS1);
    fill4_k<<<(N_NODES * HEADS1 / 4 + T - 1) / T, T>>>((float4*)emax, -INFINITY, N_NODES * HEADS1 / 4);
    cudaMemsetAsync(den, 0, (size_t)N_NODES * HEADS1 * 4);
    cudaMemsetAsync(acc1, 0, (size_t)N_NODES * F1 * 4);
    edge_max_k<<<(EP * HEADS1 + T - 1) / T, T>>>(ei, as, ad, emax, ebuf, HEADS1);
    edge_exp_k<<<(EP * HEADS1 + T - 1) / T, T>>>(ei, emax, den, ebuf, HEADS1);
    edge_aggr_k<<<((size_t)EP * HEADS1 * 32 + T - 1) / T, T>>>(ei, ebuf, den, h1, acc1, HEADS1);
    bias_elu4_k<<<(N_NODES * F1 / 4 + T - 1) / T, T>>>((float4*)acc1, b1, N_NODES * F1 / 4, F1);

    // --- GATConv2 (H=1, D=128) ---
    gemm(acc1, W2, nullptr, h2, N_NODES, DCH, F1, DCH, 0);
    alpha_k<<<(N_NODES + T - 1) / T, T>>>(h2, a_s2, a_d2, as, ad, N_NODES, 1);
    fill4_k<<<(N_NODES / 4 + T - 1) / T, T>>>((float4*)emax, -INFINITY, N_NODES / 4);
    cudaMemsetAsync(den, 0, (size_t)N_NODES * 4);
    cudaMemsetAsync(acc2, 0, (size_t)N_NODES * DCH * 4);
    edge_max_k<<<(EP + T - 1) / T, T>>>(ei, as, ad, emax, ebuf, 1);
    edge_exp_k<<<(EP + T - 1) / T, T>>>(ei, emax, den, ebuf, 1);
    edge_aggr_k<<<((size_t)EP * 32 + T - 1) / T, T>>>(ei, ebuf, den, h2, acc2, 1);
    bias_elu4_k<<<(N_NODES * DCH / 4 + T - 1) / T, T>>>((float4*)acc2, b2, N_NODES * DCH / 4, DCH);

    // --- global max pool + Wg ---
    fill4_k<<<(N_GRAPH * DCH / 4 + T - 1) / T, T>>>((float4*)pool, -INFINITY, N_GRAPH * DCH / 4);
    pool_max_k<<<(N_NODES * DCH + T - 1) / T, T>>>(acc2, batch, pool);
    gemm(pool, Wg, bg, vout, N_GRAPH, DCH, DCH, 512, 1);   // relu, strided into concat buf
}

extern "C" void kernel_launch(void* const* d_in, const int* in_sizes, int n_in,
                              void* d_out, int out_size)
{
    const float* x1   = (const float*)d_in[0];
    const int*   ei1  = (const int*)  d_in[1];
    const int*   bt1  = (const int*)  d_in[2];
    const float* x2   = (const float*)d_in[3];
    const int*   ei2  = (const int*)  d_in[4];
    const int*   bt2  = (const int*)  d_in[5];
    const float* cell = (const float*)d_in[6];
    const float* W1   = (const float*)d_in[7];
    const float* aS1  = (const float*)d_in[8];
    const float* aD1  = (const float*)d_in[9];
    const float* b1   = (const float*)d_in[10];
    const float* W2   = (const float*)d_in[11];
    const float* aS2  = (const float*)d_in[12];
    const float* aD2  = (const float*)d_in[13];
    const float* b2   = (const float*)d_in[14];
    const float* Wg   = (const float*)d_in[15];
    const float* bg   = (const float*)d_in[16];
    const float* Wr1  = (const float*)d_in[17];
    const float* br1  = (const float*)d_in[18];
    const float* Wr2  = (const float*)d_in[19];
    const float* br2  = (const float*)d_in[20];
    const float* Wr3  = (const float*)d_in[21];
    const float* br3  = (const float*)d_in[22];
    const float* Wf1  = (const float*)d_in[23];
    const float* bf1  = (const float*)d_in[24];
    const float* Wf2  = (const float*)d_in[25];
    const float* bf2  = (const float*)d_in[26];
    const float* Wf3  = (const float*)d_in[27];
    const float* bf3  = (const float*)d_in[28];
    const float* Wo   = (const float*)d_in[29];
    const float* bo   = (const float*)d_in[30];
    float* out = (float*)d_out;

    float *h1, *acc1, *h2, *acc2, *as, *ad, *emax, *den, *ebuf, *pool;
    float *cn, *c1, *c2, *xc, *f1, *f2, *f3;
    cudaGetSymbolAddress((void**)&h1,   g_h1);
    cudaGetSymbolAddress((void**)&acc1, g_acc1);
    cudaGetSymbolAddress((void**)&h2,   g_h2);
    cudaGetSymbolAddress((void**)&acc2, g_acc2);
    cudaGetSymbolAddress((void**)&as,   g_as);
    cudaGetSymbolAddress((void**)&ad,   g_ad);
    cudaGetSymbolAddress((void**)&emax, g_emax);
    cudaGetSymbolAddress((void**)&den,  g_den);
    cudaGetSymbolAddress((void**)&ebuf, g_edge);
    cudaGetSymbolAddress((void**)&pool, g_pool);
    cudaGetSymbolAddress((void**)&cn,   g_cn);
    cudaGetSymbolAddress((void**)&c1,   g_c1);
    cudaGetSymbolAddress((void**)&c2,   g_c2);
    cudaGetSymbolAddress((void**)&xc,   g_xc);
    cudaGetSymbolAddress((void**)&f1,   g_f1);
    cudaGetSymbolAddress((void**)&f2,   g_f2);
    cudaGetSymbolAddress((void**)&f3,   g_f3);

    // two GNN branches -> xc[:, 0:128) and xc[:, 128:256)
    run_branch(x1, ei1, bt1, W1, aS1, aD1, b1, W2, aS2, aD2, b2, Wg, bg,
               h1, acc1, h2, acc2, as, ad, emax, den, ebuf, pool, xc);
    run_branch(x2, ei2, bt2, W1, aS1, aD1, b1, W2, aS2, aD2, b2, Wg, bg,
               h1, acc1, h2, acc2, as, ad, emax, den, ebuf, pool, xc + 128);

    // cell branch -> xc[:, 256:512)
    l2norm_k<<<N_GRAPH, 256>>>(cell, cn, FXT);
    gemm(cn, Wr1, br1, c1, N_GRAPH, 2048, FXT, 2048, 1);
    gemm(c1, Wr2, br2, c2, N_GRAPH, 512, 2048, 512, 1);
    gemm(c2, Wr3, br3, xc + 256, N_GRAPH, 256, 512, 512, 1);

    // fuse head
    l2norm_k<<<N_GRAPH, 256>>>(xc, xc, 512);
    gemm(xc, Wf1, bf1, f1, N_GRAPH, 1024, 512, 1024, 1);
    gemm(f1, Wf2, bf2, f2, N_GRAPH, 512, 1024, 512, 1);
    gemm(f2, Wf3, bf3, f3, N_GRAPH, 128, 512, 128, 1);
    gemm(f3, Wo, bo, out, N_GRAPH, 2, 128, 2, 0);
}

// round 8
// speedup vs baseline: 1.6525x; 1.2986x over previous
#include <cuda_runtime.h>
#include <math.h>
#include <stdint.h>

#define N_NODES 30000
#define N_EDGES 100000
#define EP      (N_EDGES + N_NODES)   // edges + self loops = 130000
#define N_GRAPH 1024
#define HEADS1  10
#define DCH     128
#define F1      1280                  // HEADS1 * DCH
#define FXD     78
#define FXT     954

// ---------------- scratch (device globals; no allocations allowed) ----------
__device__ float g_h1  [(size_t)N_NODES * F1];
__device__ float g_acc1[(size_t)N_NODES * F1];
__device__ float g_h2  [N_NODES * DCH];
__device__ float g_acc2[N_NODES * DCH];
__device__ float g_as  [N_NODES * HEADS1];
__device__ float g_ad  [N_NODES * HEADS1];
__device__ float g_den [N_NODES * HEADS1];
__device__ float g_edge[EP * HEADS1];
__device__ float g_pool[N_GRAPH * DCH];
__device__ float g_cn  [N_GRAPH * FXT];
__device__ float g_c1  [N_GRAPH * 2048];
__device__ float g_c2  [N_GRAPH * 512];
__device__ float g_xc  [N_GRAPH * 512];
__device__ float g_f1  [N_GRAPH * 1024];
__device__ float g_f2  [N_GRAPH * 512];
__device__ float g_f3  [N_GRAPH * 128];

// ---------------- helpers ----------------
__device__ __forceinline__ void atomicMaxF(float* a, float v) {
    if (v >= 0.f) atomicMax((int*)a, __float_as_int(v));
    else          atomicMin((unsigned int*)a, __float_as_uint(v));
}

__device__ __forceinline__ void redAdd4(float* p, float4 v) {
    asm volatile("red.global.add.v4.f32 [%0], {%1,%2,%3,%4};"
                 :: "l"(p), "f"(v.x), "f"(v.y), "f"(v.z), "f"(v.w) : "memory");
}

__device__ __forceinline__ uint32_t f2tf32(float x) {
    uint32_t r;
    asm("cvt.rna.tf32.f32 %0, %1;" : "=r"(r) : "f"(x));
    return r;
}

__device__ __forceinline__ void mma_tf32(float c[4],
                                         uint32_t a0, uint32_t a1, uint32_t a2, uint32_t a3,
                                         uint32_t b0, uint32_t b1) {
    asm volatile("mma.sync.aligned.m16n8k8.row.col.f32.tf32.tf32.f32 "
                 "{%0,%1,%2,%3}, {%4,%5,%6,%7}, {%8,%9}, {%0,%1,%2,%3};"
                 : "+f"(c[0]), "+f"(c[1]), "+f"(c[2]), "+f"(c[3])
                 : "r"(a0), "r"(a1), "r"(a2), "r"(a3), "r"(b0), "r"(b1));
}

// ---------------- TF32 tensor-core GEMM --------------------------------------
// C = act(A[M,K] @ B[K,N] + bias), A,B row-major, C stride ldc. act: 0 none, 1 relu.
// 128x128 block tile, 256 threads = 8 warps in 2(M)x4(N); each warp 64x32 via
// 4x4 grid of m16n8k8 tf32 MMAs. TK=16 (two k=8 steps per tile).
#define TM 128
#define TN 128
#define TK 16
#define A_STR 20    // 16 + 4 pad: conflict-free A-fragment reads
#define B_STR 136   // 128 + 8 pad: conflict-free B-fragment reads

__global__ __launch_bounds__(256)
void gemm_k(const float* __restrict__ A, const float* __restrict__ B,
            const float* __restrict__ bias, float* __restrict__ C,
            int M, int N, int K, int ldc, int act)
{
    __shared__ uint32_t As[TM][A_STR];   // [m][k] tf32
    __shared__ uint32_t Bs[TK][B_STR];   // [k][n] tf32

    int tid  = threadIdx.x;
    int wid  = tid >> 5, lane = tid & 31;
    int g    = lane >> 2, tg = lane & 3;        // mma group / thread-in-group
    int warpM = wid >> 2, warpN = wid & 3;      // 2 x 4 warps
    int m0 = blockIdx.y * TM, n0 = blockIdx.x * TN;
    int rowA = warpM * 64;                      // warp's A tile row base in SMEM
    int colB = warpN * 32;                      // warp's B tile col base in SMEM

    // staging coords (same as global load pattern)
    int ar  = tid >> 1;                          // 0..127 A row
    int ac0 = (tid & 1) * 8;                     // 0/8 A col base (8 floats)
    int br  = tid >> 5;                          // 0..7 B row (+8 second)
    int bc  = (tid & 31) * 4;                    // B col base (4 floats)

    float a_reg[8];
    float4 b_reg[2];

    auto loadA = [&](int k0) {
        int gm = m0 + ar;
        if (gm < M) {
            const float* ap = A + (size_t)gm * K + k0 + ac0;
            if (((K & 3) == 0) && (k0 + ac0 + 7 < K)) {
                float4 v0 = *(const float4*)(ap);
                float4 v1 = *(const float4*)(ap + 4);
                a_reg[0] = v0.x; a_reg[1] = v0.y; a_reg[2] = v0.z; a_reg[3] = v0.w;
                a_reg[4] = v1.x; a_reg[5] = v1.y; a_reg[6] = v1.z; a_reg[7] = v1.w;
            } else {
                #pragma unroll
                for (int j = 0; j < 8; j++) {
                    int gk = k0 + ac0 + j;
                    a_reg[j] = (gk < K) ? ap[j] : 0.f;
                }
            }
        } else {
            #pragma unroll
            for (int j = 0; j < 8; j++) a_reg[j] = 0.f;
        }
    };
    auto loadB = [&](int k0) {
        #pragma unroll
        for (int it = 0; it < 2; it++) {
            int gk = k0 + br + it * 8;
            int gn = n0 + bc;
            float4 v = make_float4(0.f, 0.f, 0.f, 0.f);
            if (gk < K) {
                const float* bp = B + (size_t)gk * N + gn;
                if (gn + 3 < N) v = *(const float4*)bp;
                else {
                    if (gn     < N) v.x = bp[0];
                    if (gn + 1 < N) v.y = bp[1];
                    if (gn + 2 < N) v.z = bp[2];
                }
            }
            b_reg[it] = v;
        }
    };
    auto storeA = [&]() {
        #pragma unroll
        for (int j = 0; j < 8; j++) As[ar][ac0 + j] = f2tf32(a_reg[j]);
    };
    auto storeB = [&]() {
        Bs[br][bc]     = f2tf32(b_reg[0].x); Bs[br][bc + 1]     = f2tf32(b_reg[0].y);
        Bs[br][bc + 2] = f2tf32(b_reg[0].z); Bs[br][bc + 3]     = f2tf32(b_reg[0].w);
        Bs[br + 8][bc]     = f2tf32(b_reg[1].x); Bs[br + 8][bc + 1] = f2tf32(b_reg[1].y);
        Bs[br + 8][bc + 2] = f2tf32(b_reg[1].z); Bs[br + 8][bc + 3] = f2tf32(b_reg[1].w);
    };

    float acc[4][4][4] = {};   // [mTile][nTile][c0..c3]

    int nk = (K + TK - 1) / TK;
    loadA(0); loadB(0);
    storeA(); storeB();
    __syncthreads();

    for (int t = 1; t <= nk; t++) {
        if (t < nk) { loadA(t * TK); loadB(t * TK); }
        #pragma unroll
        for (int ks = 0; ks < TK; ks += 8) {
            uint32_t af[4][4], bf[4][2];
            #pragma unroll
            for (int i = 0; i < 4; i++) {
                int r = rowA + i * 16 + g;
                af[i][0] = As[r][ks + tg];
                af[i][1] = As[r + 8][ks + tg];
                af[i][2] = As[r][ks + tg + 4];
                af[i][3] = As[r + 8][ks + tg + 4];
            }
            #pragma unroll
            for (int u = 0; u < 4; u++) {
                int c = colB + u * 8 + g;
                bf[u][0] = Bs[ks + tg][c];
                bf[u][1] = Bs[ks + tg + 4][c];
            }
            #pragma unroll
            for (int i = 0; i < 4; i++)
                #pragma unroll
                for (int u = 0; u < 4; u++)
                    mma_tf32(acc[i][u], af[i][0], af[i][1], af[i][2], af[i][3],
                             bf[u][0], bf[u][1]);
        }
        __syncthreads();
        if (t < nk) { storeA(); storeB(); __syncthreads(); }
    }

    // epilogue: c0,c1 -> (row, col..col+1), c2,c3 -> (row+8, ...)
    #pragma unroll
    for (int i = 0; i < 4; i++) {
        int mrow = m0 + rowA + i * 16 + g;
        #pragma unroll
        for (int u = 0; u < 4; u++) {
            int n = n0 + colB + u * 8 + tg * 2;
            float b0 = 0.f, b1 = 0.f;
            if (bias) { if (n < N) b0 = bias[n]; if (n + 1 < N) b1 = bias[n + 1]; }
            #pragma unroll
            for (int half = 0; half < 2; half++) {
                int m = mrow + half * 8;
                if (m >= M) continue;
                float vx = acc[i][u][half * 2]     + b0;
                float vy = acc[i][u][half * 2 + 1] + b1;
                if (act == 1) { vx = fmaxf(vx, 0.f); vy = fmaxf(vy, 0.f); }
                if (n     < N) C[(size_t)m * ldc + n]     = vx;
                if (n + 1 < N) C[(size_t)m * ldc + n + 1] = vy;
            }
        }
    }
}

// ---------------- elementwise ----------------
__global__ void fill4_k(float4* __restrict__ p, float v, int n4) {
    int t = blockIdx.x * blockDim.x + threadIdx.x;
    if (t < n4) p[t] = make_float4(v, v, v, v);
}

// alpha_s / alpha_d per (node, head)
__global__ void alpha_k(const float* __restrict__ h,
                        const float* __restrict__ a_s, const float* __restrict__ a_d,
                        float* __restrict__ os, float* __restrict__ od,
                        int n, int heads)
{
    int t = blockIdx.x * blockDim.x + threadIdx.x;
    if (t >= n * heads) return;
    int hd = t % heads;
    const float* hp = h + (size_t)t * DCH;
    const float* sp = a_s + hd * DCH;
    const float* dp = a_d + hd * DCH;
    float s1 = 0.f, s2 = 0.f;
    #pragma unroll 8
    for (int c = 0; c < DCH; c += 4) {
        float4 hv = *(const float4*)(hp + c);
        float4 sv = *(const float4*)(sp + c);
        float4 dv = *(const float4*)(dp + c);
        s1 += hv.x * sv.x + hv.y * sv.y + hv.z * sv.z + hv.w * sv.w;
        s2 += hv.x * dv.x + hv.y * dv.y + hv.z * dv.z + hv.w * dv.w;
    }
    os[t] = s1;
    od[t] = s2;
}

__device__ __forceinline__ void edge_ends(int e, const int* __restrict__ ei,
                                          int& src, int& dst)
{
    if (e < N_EDGES) { src = ei[e]; dst = ei[N_EDGES + e]; }
    else             { src = dst = e - N_EDGES; }
}

// fused: e = leaky_relu(as[src]+ad[dst]); ex = exp(e) (softmax is shift-invariant,
// logits here are O(1) so the max-subtraction pass is dropped); den += ex
__global__ void edge_score_k(const int* __restrict__ ei,
                             const float* __restrict__ as, const float* __restrict__ ad,
                             float* __restrict__ den, float* __restrict__ ebuf, int heads)
{
    int t = blockIdx.x * blockDim.x + threadIdx.x;
    if (t >= EP * heads) return;
    int e = t / heads, hd = t - e * heads;
    int src, dst; edge_ends(e, ei, src, dst);
    float v = as[src * heads + hd] + ad[dst * heads + hd];
    v = v > 0.f ? v : 0.2f * v;           // leaky_relu 0.2
    float ex = __expf(v);
    ebuf[t] = ex;
    atomicAdd(&den[dst * heads + hd], ex);
}

// one warp per (edge, head); lane covers 4 channels
__global__ void edge_aggr_k(const int* __restrict__ ei,
                            const float* __restrict__ ebuf, const float* __restrict__ den,
                            const float* __restrict__ h, float* __restrict__ acc, int heads)
{
    int w = (blockIdx.x * blockDim.x + threadIdx.x) >> 5;
    int lane = threadIdx.x & 31;
    if (w >= EP * heads) return;
    int e = w / heads, hd = w - e * heads;
    int src, dst; edge_ends(e, ei, src, dst);
    float alpha = ebuf[w] / (den[dst * heads + hd] + 1e-16f);
    const float4 v = *(const float4*)(h + ((size_t)src * heads + hd) * DCH + lane * 4);
    float4 m = make_float4(v.x * alpha, v.y * alpha, v.z * alpha, v.w * alpha);
    redAdd4(acc + ((size_t)dst * heads + hd) * DCH + lane * 4, m);
}

__global__ void bias_elu4_k(float4* __restrict__ x, const float* __restrict__ b,
                            int n4, int C)
{
    int t = blockIdx.x * blockDim.x + threadIdx.x;
    if (t >= n4) return;
    int c = (t * 4) % C;
    float4 v = x[t];
    const float4 bb = *(const float4*)(b + c);
    v.x += bb.x; v.y += bb.y; v.z += bb.z; v.w += bb.w;
    v.x = v.x > 0.f ? v.x : __expf(v.x) - 1.f;
    v.y = v.y > 0.f ? v.y : __expf(v.y) - 1.f;
    v.z = v.z > 0.f ? v.z : __expf(v.z) - 1.f;
    v.w = v.w > 0.f ? v.w : __expf(v.w) - 1.f;
    x[t] = v;
}

__global__ void pool_max_k(const float* __restrict__ h, const int* __restrict__ batch,
                           float* __restrict__ pool)
{
    int t = blockIdx.x * blockDim.x + threadIdx.x;
    if (t >= N_NODES * DCH) return;
    int nidx = t >> 7, c = t & 127;
    atomicMaxF(&pool[batch[nidx] * DCH + c], h[t]);
}

// row-wise L2 normalize (block per row); safe in-place
__global__ void l2norm_k(const float* __restrict__ in, float* __restrict__ out, int cols)
{
    __shared__ float red[256];
    int row = blockIdx.x;
    const float* ip = in + (size_t)row * cols;
    float s = 0.f;
    for (int c = threadIdx.x; c < cols; c += 256) { float v = ip[c]; s += v * v; }
    red[threadIdx.x] = s;
    __syncthreads();
    for (int off = 128; off > 0; off >>= 1) {
        if (threadIdx.x < off) red[threadIdx.x] += red[threadIdx.x + off];
        __syncthreads();
    }
    float sc = 1.f / fmaxf(sqrtf(red[0]), 1e-12f);
    float* op = out + (size_t)row * cols;
    for (int c = threadIdx.x; c < cols; c += 256) op[c] = ip[c] * sc;
}

// ---------------- host orchestration ----------------
static void gemm(const float* A, const float* B, const float* bias, float* C,
                 int M, int N, int K, int ldc, int act)
{
    dim3 grid((N + TN - 1) / TN, (M + TM - 1) / TM);
    gemm_k<<<grid, 256>>>(A, B, bias, C, M, N, K, ldc, act);
}

static void run_branch(const float* x, const int* ei, const int* batch,
                       const float* W1, const float* a_s1, const float* a_d1, const float* b1,
                       const float* W2, const float* a_s2, const float* a_d2, const float* b2,
                       const float* Wg, const float* bg,
                       float* h1, float* acc1, float* h2, float* acc2,
                       float* as, float* ad, float* den, float* ebuf,
                       float* pool, float* vout)
{
    const int T = 256;
    // --- GATConv1 (H=10, D=128) ---
    gemm(x, W1, nullptr, h1, N_NODES, F1, FXD, F1, 0);
    alpha_k<<<(N_NODES * HEADS1 + T - 1) / T, T>>>(h1, a_s1, a_d1, as, ad, N_NODES, HEADS1);
    cudaMemsetAsync(den, 0, (size_t)N_NODES * HEADS1 * 4);
    cudaMemsetAsync(acc1, 0, (size_t)N_NODES * F1 * 4);
    edge_score_k<<<(EP * HEADS1 + T - 1) / T, T>>>(ei, as, ad, den, ebuf, HEADS1);
    edge_aggr_k<<<((size_t)EP * HEADS1 * 32 + T - 1) / T, T>>>(ei, ebuf, den, h1, acc1, HEADS1);
    bias_elu4_k<<<(N_NODES * F1 / 4 + T - 1) / T, T>>>((float4*)acc1, b1, N_NODES * F1 / 4, F1);

    // --- GATConv2 (H=1, D=128) ---
    gemm(acc1, W2, nullptr, h2, N_NODES, DCH, F1, DCH, 0);
    alpha_k<<<(N_NODES + T - 1) / T, T>>>(h2, a_s2, a_d2, as, ad, N_NODES, 1);
    cudaMemsetAsync(den, 0, (size_t)N_NODES * 4);
    cudaMemsetAsync(acc2, 0, (size_t)N_NODES * DCH * 4);
    edge_score_k<<<(EP + T - 1) / T, T>>>(ei, as, ad, den, ebuf, 1);
    edge_aggr_k<<<((size_t)EP * 32 + T - 1) / T, T>>>(ei, ebuf, den, h2, acc2, 1);
    bias_elu4_k<<<(N_NODES * DCH / 4 + T - 1) / T, T>>>((float4*)acc2, b2, N_NODES * DCH / 4, DCH);

    // --- global max pool + Wg ---
    fill4_k<<<(N_GRAPH * DCH / 4 + T - 1) / T, T>>>((float4*)pool, -INFINITY, N_GRAPH * DCH / 4);
    pool_max_k<<<(N_NODES * DCH + T - 1) / T, T>>>(acc2, batch, pool);
    gemm(pool, Wg, bg, vout, N_GRAPH, DCH, DCH, 512, 1);   // relu, strided into concat buf
}

extern "C" void kernel_launch(void* const* d_in, const int* in_sizes, int n_in,
                              void* d_out, int out_size)
{
    const float* x1   = (const float*)d_in[0];
    const int*   ei1  = (const int*)  d_in[1];
    const int*   bt1  = (const int*)  d_in[2];
    const float* x2   = (const float*)d_in[3];
    const int*   ei2  = (const int*)  d_in[4];
    const int*   bt2  = (const int*)  d_in[5];
    const float* cell = (const float*)d_in[6];
    const float* W1   = (const float*)d_in[7];
    const float* aS1  = (const float*)d_in[8];
    const float* aD1  = (const float*)d_in[9];
    const float* b1   = (const float*)d_in[10];
    const float* W2   = (const float*)d_in[11];
    const float* aS2  = (const float*)d_in[12];
    const float* aD2  = (const float*)d_in[13];
    const float* b2   = (const float*)d_in[14];
    const float* Wg   = (const float*)d_in[15];
    const float* bg   = (const float*)d_in[16];
    const float* Wr1  = (const float*)d_in[17];
    const float* br1  = (const float*)d_in[18];
    const float* Wr2  = (const float*)d_in[19];
    const float* br2  = (const float*)d_in[20];
    const float* Wr3  = (const float*)d_in[21];
    const float* br3  = (const float*)d_in[22];
    const float* Wf1  = (const float*)d_in[23];
    const float* bf1  = (const float*)d_in[24];
    const float* Wf2  = (const float*)d_in[25];
    const float* bf2  = (const float*)d_in[26];
    const float* Wf3  = (const float*)d_in[27];
    const float* bf3  = (const float*)d_in[28];
    const float* Wo   = (const float*)d_in[29];
    const float* bo   = (const float*)d_in[30];
    float* out = (float*)d_out;

    float *h1, *acc1, *h2, *acc2, *as, *ad, *den, *ebuf, *pool;
    float *cn, *c1, *c2, *xc, *f1, *f2, *f3;
    cudaGetSymbolAddress((void**)&h1,   g_h1);
    cudaGetSymbolAddress((void**)&acc1, g_acc1);
    cudaGetSymbolAddress((void**)&h2,   g_h2);
    cudaGetSymbolAddress((void**)&acc2, g_acc2);
    cudaGetSymbolAddress((void**)&as,   g_as);
    cudaGetSymbolAddress((void**)&ad,   g_ad);
    cudaGetSymbolAddress((void**)&den,  g_den);
    cudaGetSymbolAddress((void**)&ebuf, g_edge);
    cudaGetSymbolAddress((void**)&pool, g_pool);
    cudaGetSymbolAddress((void**)&cn,   g_cn);
    cudaGetSymbolAddress((void**)&c1,   g_c1);
    cudaGetSymbolAddress((void**)&c2,   g_c2);
    cudaGetSymbolAddress((void**)&xc,   g_xc);
    cudaGetSymbolAddress((void**)&f1,   g_f1);
    cudaGetSymbolAddress((void**)&f2,   g_f2);
    cudaGetSymbolAddress((void**)&f3,   g_f3);

    // two GNN branches -> xc[:, 0:128) and xc[:, 128:256)
    run_branch(x1, ei1, bt1, W1, aS1, aD1, b1, W2, aS2, aD2, b2, Wg, bg,
               h1, acc1, h2, acc2, as, ad, den, ebuf, pool, xc);
    run_branch(x2, ei2, bt2, W1, aS1, aD1, b1, W2, aS2, aD2, b2, Wg, bg,
               h1, acc1, h2, acc2, as, ad, den, ebuf, pool, xc + 128);

    // cell branch -> xc[:, 256:512)
    l2norm_k<<<N_GRAPH, 256>>>(cell, cn, FXT);
    gemm(cn, Wr1, br1, c1, N_GRAPH, 2048, FXT, 2048, 1);
    gemm(c1, Wr2, br2, c2, N_GRAPH, 512, 2048, 512, 1);
    gemm(c2, Wr3, br3, xc + 256, N_GRAPH, 256, 512, 512, 1);

    // fuse head
    l2norm_k<<<N_GRAPH, 256>>>(xc, xc, 512);
    gemm(xc, Wf1, bf1, f1, N_GRAPH, 1024, 512, 1024, 1);
    gemm(f1, Wf2, bf2, f2, N_GRAPH, 512, 1024, 512, 1);
    gemm(f2, Wf3, bf3, f3, N_GRAPH, 128, 512, 128, 1);
    gemm(f3, Wo, bo, out, N_GRAPH, 2, 128, 2, 0);
}

// round 9
// speedup vs baseline: 2.0303x; 1.2286x over previous
#include <cuda_runtime.h>
#include <math.h>
#include <stdint.h>

#define N_NODES 30000
#define N_EDGES 100000
#define EP      (N_EDGES + N_NODES)   // edges + self loops = 130000
#define N_GRAPH 1024
#define HEADS1  10
#define DCH     128
#define F1      1280                  // HEADS1 * DCH
#define FXD     78
#define FXT     954

// ---------------- scratch (device globals; no allocations allowed) ----------
__device__ float g_h1  [(size_t)N_NODES * F1];
__device__ float g_acc1[(size_t)N_NODES * F1];
__device__ float g_h2  [N_NODES * DCH];
__device__ float g_as  [N_NODES * HEADS1];
__device__ float g_ad  [N_NODES * HEADS1];
__device__ int   g_deg [N_NODES];
__device__ int   g_cur [N_NODES];
__device__ int   g_off [N_NODES + 1];
__device__ int   g_csrc[EP];
__device__ float g_pool[N_GRAPH * DCH];
__device__ float g_cn  [N_GRAPH * FXT];
__device__ float g_c1  [N_GRAPH * 2048];
__device__ float g_c2  [N_GRAPH * 512];
__device__ float g_xc  [N_GRAPH * 512];
__device__ float g_f1  [N_GRAPH * 1024];
__device__ float g_f2  [N_GRAPH * 512];
__device__ float g_f3  [N_GRAPH * 128];

// ---------------- helpers ----------------
__device__ __forceinline__ void atomicMaxF(float* a, float v) {
    if (v >= 0.f) atomicMax((int*)a, __float_as_int(v));
    else          atomicMin((unsigned int*)a, __float_as_uint(v));
}

__device__ __forceinline__ uint32_t f2tf32(float x) {
    uint32_t r;
    asm("cvt.rna.tf32.f32 %0, %1;" : "=r"(r) : "f"(x));
    return r;
}

__device__ __forceinline__ void mma_tf32(float c[4],
                                         uint32_t a0, uint32_t a1, uint32_t a2, uint32_t a3,
                                         uint32_t b0, uint32_t b1) {
    asm volatile("mma.sync.aligned.m16n8k8.row.col.f32.tf32.tf32.f32 "
                 "{%0,%1,%2,%3}, {%4,%5,%6,%7}, {%8,%9}, {%0,%1,%2,%3};"
                 : "+f"(c[0]), "+f"(c[1]), "+f"(c[2]), "+f"(c[3])
                 : "r"(a0), "r"(a1), "r"(a2), "r"(a3), "r"(b0), "r"(b1));
}

// ---------------- TF32 tensor-core GEMM --------------------------------------
#define TM 128
#define TN 128
#define TK 16
#define A_STR 20
#define B_STR 136

__global__ __launch_bounds__(256)
void gemm_k(const float* __restrict__ A, const float* __restrict__ B,
            const float* __restrict__ bias, float* __restrict__ C,
            int M, int N, int K, int ldc, int act)
{
    __shared__ uint32_t As[TM][A_STR];
    __shared__ uint32_t Bs[TK][B_STR];

    int tid  = threadIdx.x;
    int wid  = tid >> 5, lane = tid & 31;
    int g    = lane >> 2, tg = lane & 3;
    int warpM = wid >> 2, warpN = wid & 3;
    int m0 = blockIdx.y * TM, n0 = blockIdx.x * TN;
    int rowA = warpM * 64;
    int colB = warpN * 32;

    int ar  = tid >> 1;
    int ac0 = (tid & 1) * 8;
    int br  = tid >> 5;
    int bc  = (tid & 31) * 4;

    float a_reg[8];
    float4 b_reg[2];

    auto loadA = [&](int k0) {
        int gm = m0 + ar;
        if (gm < M) {
            const float* ap = A + (size_t)gm * K + k0 + ac0;
            if (((K & 3) == 0) && (k0 + ac0 + 7 < K)) {
                float4 v0 = *(const float4*)(ap);
                float4 v1 = *(const float4*)(ap + 4);
                a_reg[0] = v0.x; a_reg[1] = v0.y; a_reg[2] = v0.z; a_reg[3] = v0.w;
                a_reg[4] = v1.x; a_reg[5] = v1.y; a_reg[6] = v1.z; a_reg[7] = v1.w;
            } else {
                #pragma unroll
                for (int j = 0; j < 8; j++) {
                    int gk = k0 + ac0 + j;
                    a_reg[j] = (gk < K) ? ap[j] : 0.f;
                }
            }
        } else {
            #pragma unroll
            for (int j = 0; j < 8; j++) a_reg[j] = 0.f;
        }
    };
    auto loadB = [&](int k0) {
        #pragma unroll
        for (int it = 0; it < 2; it++) {
            int gk = k0 + br + it * 8;
            int gn = n0 + bc;
            float4 v = make_float4(0.f, 0.f, 0.f, 0.f);
            if (gk < K) {
                const float* bp = B + (size_t)gk * N + gn;
                if (gn + 3 < N) v = *(const float4*)bp;
                else {
                    if (gn     < N) v.x = bp[0];
                    if (gn + 1 < N) v.y = bp[1];
                    if (gn + 2 < N) v.z = bp[2];
                }
            }
            b_reg[it] = v;
        }
    };
    auto storeA = [&]() {
        #pragma unroll
        for (int j = 0; j < 8; j++) As[ar][ac0 + j] = f2tf32(a_reg[j]);
    };
    auto storeB = [&]() {
        Bs[br][bc]     = f2tf32(b_reg[0].x); Bs[br][bc + 1]     = f2tf32(b_reg[0].y);
        Bs[br][bc + 2] = f2tf32(b_reg[0].z); Bs[br][bc + 3]     = f2tf32(b_reg[0].w);
        Bs[br + 8][bc]     = f2tf32(b_reg[1].x); Bs[br + 8][bc + 1] = f2tf32(b_reg[1].y);
        Bs[br + 8][bc + 2] = f2tf32(b_reg[1].z); Bs[br + 8][bc + 3] = f2tf32(b_reg[1].w);
    };

    float acc[4][4][4] = {};

    int nk = (K + TK - 1) / TK;
    loadA(0); loadB(0);
    storeA(); storeB();
    __syncthreads();

    for (int t = 1; t <= nk; t++) {
        if (t < nk) { loadA(t * TK); loadB(t * TK); }
        #pragma unroll
        for (int ks = 0; ks < TK; ks += 8) {
            uint32_t af[4][4], bf[4][2];
            #pragma unroll
            for (int i = 0; i < 4; i++) {
                int r = rowA + i * 16 + g;
                af[i][0] = As[r][ks + tg];
                af[i][1] = As[r + 8][ks + tg];
                af[i][2] = As[r][ks + tg + 4];
                af[i][3] = As[r + 8][ks + tg + 4];
            }
            #pragma unroll
            for (int u = 0; u < 4; u++) {
                int c = colB + u * 8 + g;
                bf[u][0] = Bs[ks + tg][c];
                bf[u][1] = Bs[ks + tg + 4][c];
            }
            #pragma unroll
            for (int i = 0; i < 4; i++)
                #pragma unroll
                for (int u = 0; u < 4; u++)
                    mma_tf32(acc[i][u], af[i][0], af[i][1], af[i][2], af[i][3],
                             bf[u][0], bf[u][1]);
        }
        __syncthreads();
        if (t < nk) { storeA(); storeB(); __syncthreads(); }
    }

    #pragma unroll
    for (int i = 0; i < 4; i++) {
        int mrow = m0 + rowA + i * 16 + g;
        #pragma unroll
        for (int u = 0; u < 4; u++) {
            int n = n0 + colB + u * 8 + tg * 2;
            float b0 = 0.f, b1 = 0.f;
            if (bias) { if (n < N) b0 = bias[n]; if (n + 1 < N) b1 = bias[n + 1]; }
            #pragma unroll
            for (int half = 0; half < 2; half++) {
                int m = mrow + half * 8;
                if (m >= M) continue;
                float vx = acc[i][u][half * 2]     + b0;
                float vy = acc[i][u][half * 2 + 1] + b1;
                if (act == 1) { vx = fmaxf(vx, 0.f); vy = fmaxf(vy, 0.f); }
                if (n     < N) C[(size_t)m * ldc + n]     = vx;
                if (n + 1 < N) C[(size_t)m * ldc + n + 1] = vy;
            }
        }
    }
}

// ---------------- CSR build ----------------
__device__ __forceinline__ void edge_ends(int e, const int* __restrict__ ei,
                                          int& src, int& dst)
{
    if (e < N_EDGES) { src = ei[e]; dst = ei[N_EDGES + e]; }
    else             { src = dst = e - N_EDGES; }
}

__global__ void hist_k(const int* __restrict__ ei, int* __restrict__ deg) {
    int e = blockIdx.x * blockDim.x + threadIdx.x;
    if (e >= EP) return;
    int src, dst; edge_ends(e, ei, src, dst);
    (void)src;
    atomicAdd(&deg[dst], 1);
}

// single-block exclusive scan over N_NODES ints -> off[0..N_NODES]
__global__ void scan_k(const int* __restrict__ deg, int* __restrict__ off) {
    __shared__ int sm[1024];
    __shared__ int carry;
    if (threadIdx.x == 0) { carry = 0; off[0] = 0; }
    __syncthreads();
    for (int base = 0; base < N_NODES; base += 1024) {
        int i = base + threadIdx.x;
        int v = (i < N_NODES) ? deg[i] : 0;
        sm[threadIdx.x] = v;
        __syncthreads();
        #pragma unroll
        for (int s = 1; s < 1024; s <<= 1) {
            int t = (threadIdx.x >= s) ? sm[threadIdx.x - s] : 0;
            __syncthreads();
            sm[threadIdx.x] += t;
            __syncthreads();
        }
        if (i < N_NODES) off[i + 1] = carry + sm[threadIdx.x];
        __syncthreads();
        if (threadIdx.x == 0) carry += sm[1023];
        __syncthreads();
    }
}

__global__ void scatter_k(const int* __restrict__ ei, const int* __restrict__ off,
                          int* __restrict__ cur, int* __restrict__ csrc) {
    int e = blockIdx.x * blockDim.x + threadIdx.x;
    if (e >= EP) return;
    int src, dst; edge_ends(e, ei, src, dst);
    int pos = off[dst] + atomicAdd(&cur[dst], 1);
    csrc[pos] = src;
}

// ---------------- fused GAT softmax-aggregate ----------------
// warp per (node, head): out[n,hd,:] = elu( sum_e ex_e * h[src_e,hd,:] / sum_e ex_e + bias )
__global__ void gat_aggr_k(const int* __restrict__ off, const int* __restrict__ csrc,
                           const float* __restrict__ as, const float* __restrict__ ad,
                           const float* __restrict__ h, const float* __restrict__ bias,
                           float* __restrict__ outbuf, int heads)
{
    int w = (blockIdx.x * blockDim.x + threadIdx.x) >> 5;
    int lane = threadIdx.x & 31;
    if (w >= N_NODES * heads) return;
    int n = w / heads, hd = w - n * heads;
    int r0 = off[n], r1 = off[n + 1];
    float adn = ad[n * heads + hd];
    float4 acc = make_float4(0.f, 0.f, 0.f, 0.f);
    float den = 0.f;
    for (int e = r0; e < r1; e++) {
        int src = csrc[e];
        float v = as[src * heads + hd] + adn;
        v = v > 0.f ? v : 0.2f * v;
        float ex = __expf(v);
        den += ex;
        const float4 hv = *(const float4*)(h + ((size_t)src * heads + hd) * DCH + lane * 4);
        acc.x += ex * hv.x; acc.y += ex * hv.y; acc.z += ex * hv.z; acc.w += ex * hv.w;
    }
    float inv = 1.f / (den + 1e-16f);
    const float4 bb = *(const float4*)(bias + hd * DCH + lane * 4);
    float o0 = acc.x * inv + bb.x, o1 = acc.y * inv + bb.y;
    float o2 = acc.z * inv + bb.z, o3 = acc.w * inv + bb.w;
    o0 = o0 > 0.f ? o0 : __expf(o0) - 1.f;
    o1 = o1 > 0.f ? o1 : __expf(o1) - 1.f;
    o2 = o2 > 0.f ? o2 : __expf(o2) - 1.f;
    o3 = o3 > 0.f ? o3 : __expf(o3) - 1.f;
    *(float4*)(outbuf + ((size_t)n * heads + hd) * DCH + lane * 4) =
        make_float4(o0, o1, o2, o3);
}

// layer-2 variant (heads=1) fused with global max pool
__global__ void gat_aggr_pool_k(const int* __restrict__ off, const int* __restrict__ csrc,
                                const float* __restrict__ as, const float* __restrict__ ad,
                                const float* __restrict__ h, const float* __restrict__ bias,
                                const int* __restrict__ batch, float* __restrict__ pool)
{
    int n = (blockIdx.x * blockDim.x + threadIdx.x) >> 5;
    int lane = threadIdx.x & 31;
    if (n >= N_NODES) return;
    int r0 = off[n], r1 = off[n + 1];
    float adn = ad[n];
    float4 acc = make_float4(0.f, 0.f, 0.f, 0.f);
    float den = 0.f;
    for (int e = r0; e < r1; e++) {
        int src = csrc[e];
        float v = as[src] + adn;
        v = v > 0.f ? v : 0.2f * v;
        float ex = __expf(v);
        den += ex;
        const float4 hv = *(const float4*)(h + (size_t)src * DCH + lane * 4);
        acc.x += ex * hv.x; acc.y += ex * hv.y; acc.z += ex * hv.z; acc.w += ex * hv.w;
    }
    float inv = 1.f / (den + 1e-16f);
    const float4 bb = *(const float4*)(bias + lane * 4);
    float o[4];
    o[0] = acc.x * inv + bb.x; o[1] = acc.y * inv + bb.y;
    o[2] = acc.z * inv + bb.z; o[3] = acc.w * inv + bb.w;
    float* pp = pool + (size_t)batch[n] * DCH + lane * 4;
    #pragma unroll
    for (int j = 0; j < 4; j++) {
        float v = o[j] > 0.f ? o[j] : __expf(o[j]) - 1.f;
        atomicMaxF(pp + j, v);
    }
}

// ---------------- elementwise ----------------
__global__ void fill4_k(float4* __restrict__ p, float v, int n4) {
    int t = blockIdx.x * blockDim.x + threadIdx.x;
    if (t < n4) p[t] = make_float4(v, v, v, v);
}

__global__ void alpha_k(const float* __restrict__ h,
                        const float* __restrict__ a_s, const float* __restrict__ a_d,
                        float* __restrict__ os, float* __restrict__ od,
                        int n, int heads)
{
    int t = blockIdx.x * blockDim.x + threadIdx.x;
    if (t >= n * heads) return;
    int hd = t % heads;
    const float* hp = h + (size_t)t * DCH;
    const float* sp = a_s + hd * DCH;
    const float* dp = a_d + hd * DCH;
    float s1 = 0.f, s2 = 0.f;
    #pragma unroll 8
    for (int c = 0; c < DCH; c += 4) {
        float4 hv = *(const float4*)(hp + c);
        float4 sv = *(const float4*)(sp + c);
        float4 dv = *(const float4*)(dp + c);
        s1 += hv.x * sv.x + hv.y * sv.y + hv.z * sv.z + hv.w * sv.w;
        s2 += hv.x * dv.x + hv.y * dv.y + hv.z * dv.z + hv.w * dv.w;
    }
    os[t] = s1;
    od[t] = s2;
}

// row-wise L2 normalize (block per row); safe in-place
__global__ void l2norm_k(const float* __restrict__ in, float* __restrict__ out, int cols)
{
    __shared__ float red[256];
    int row = blockIdx.x;
    const float* ip = in + (size_t)row * cols;
    float s = 0.f;
    for (int c = threadIdx.x; c < cols; c += 256) { float v = ip[c]; s += v * v; }
    red[threadIdx.x] = s;
    __syncthreads();
    for (int off = 128; off > 0; off >>= 1) {
        if (threadIdx.x < off) red[threadIdx.x] += red[threadIdx.x + off];
        __syncthreads();
    }
    float sc = 1.f / fmaxf(sqrtf(red[0]), 1e-12f);
    float* op = out + (size_t)row * cols;
    for (int c = threadIdx.x; c < cols; c += 256) op[c] = ip[c] * sc;
}

// ---------------- host orchestration ----------------
static void gemm(const float* A, const float* B, const float* bias, float* C,
                 int M, int N, int K, int ldc, int act)
{
    dim3 grid((N + TN - 1) / TN, (M + TM - 1) / TM);
    gemm_k<<<grid, 256>>>(A, B, bias, C, M, N, K, ldc, act);
}

static void run_branch(const float* x, const int* ei, const int* batch,
                       const float* W1, const float* a_s1, const float* a_d1, const float* b1,
                       const float* W2, const float* a_s2, const float* a_d2, const float* b2,
                       const float* Wg, const float* bg,
                       float* h1, float* acc1, float* h2,
                       float* as, float* ad,
                       int* deg, int* cur, int* off, int* csrc,
                       float* pool, float* vout)
{
    const int T = 256;
    // --- CSR build (shared by both layers) ---
    cudaMemsetAsync(deg, 0, N_NODES * 4);
    cudaMemsetAsync(cur, 0, N_NODES * 4);
    hist_k<<<(EP + T - 1) / T, T>>>(ei, deg);
    scan_k<<<1, 1024>>>(deg, off);
    scatter_k<<<(EP + T - 1) / T, T>>>(ei, off, cur, csrc);

    // --- GATConv1 (H=10, D=128) ---
    gemm(x, W1, nullptr, h1, N_NODES, F1, FXD, F1, 0);
    alpha_k<<<(N_NODES * HEADS1 + T - 1) / T, T>>>(h1, a_s1, a_d1, as, ad, N_NODES, HEADS1);
    gat_aggr_k<<<((size_t)N_NODES * HEADS1 * 32 + T - 1) / T, T>>>(off, csrc, as, ad, h1, b1,
                                                                   acc1, HEADS1);

    // --- GATConv2 (H=1, D=128) + fused max pool ---
    gemm(acc1, W2, nullptr, h2, N_NODES, DCH, F1, DCH, 0);
    alpha_k<<<(N_NODES + T - 1) / T, T>>>(h2, a_s2, a_d2, as, ad, N_NODES, 1);
    fill4_k<<<(N_GRAPH * DCH / 4 + T - 1) / T, T>>>((float4*)pool, -INFINITY, N_GRAPH * DCH / 4);
    gat_aggr_pool_k<<<((size_t)N_NODES * 32 + T - 1) / T, T>>>(off, csrc, as, ad, h2, b2,
                                                               batch, pool);
    gemm(pool, Wg, bg, vout, N_GRAPH, DCH, DCH, 512, 1);   // relu, strided into concat buf
}

extern "C" void kernel_launch(void* const* d_in, const int* in_sizes, int n_in,
                              void* d_out, int out_size)
{
    const float* x1   = (const float*)d_in[0];
    const int*   ei1  = (const int*)  d_in[1];
    const int*   bt1  = (const int*)  d_in[2];
    const float* x2   = (const float*)d_in[3];
    const int*   ei2  = (const int*)  d_in[4];
    const int*   bt2  = (const int*)  d_in[5];
    const float* cell = (const float*)d_in[6];
    const float* W1   = (const float*)d_in[7];
    const float* aS1  = (const float*)d_in[8];
    const float* aD1  = (const float*)d_in[9];
    const float* b1   = (const float*)d_in[10];
    const float* W2   = (const float*)d_in[11];
    const float* aS2  = (const float*)d_in[12];
    const float* aD2  = (const float*)d_in[13];
    const float* b2   = (const float*)d_in[14];
    const float* Wg   = (const float*)d_in[15];
    const float* bg   = (const float*)d_in[16];
    const float* Wr1  = (const float*)d_in[17];
    const float* br1  = (const float*)d_in[18];
    const float* Wr2  = (const float*)d_in[19];
    const float* br2  = (const float*)d_in[20];
    const float* Wr3  = (const float*)d_in[21];
    const float* br3  = (const float*)d_in[22];
    const float* Wf1  = (const float*)d_in[23];
    const float* bf1  = (const float*)d_in[24];
    const float* Wf2  = (const float*)d_in[25];
    const float* bf2  = (const float*)d_in[26];
    const float* Wf3  = (const float*)d_in[27];
    const float* bf3  = (const float*)d_in[28];
    const float* Wo   = (const float*)d_in[29];
    const float* bo   = (const float*)d_in[30];
    float* out = (float*)d_out;

    float *h1, *acc1, *h2, *as, *ad, *pool;
    float *cn, *c1, *c2, *xc, *f1, *f2, *f3;
    int *deg, *cur, *off, *csrc;
    cudaGetSymbolAddress((void**)&h1,   g_h1);
    cudaGetSymbolAddress((void**)&acc1, g_acc1);
    cudaGetSymbolAddress((void**)&h2,   g_h2);
    cudaGetSymbolAddress((void**)&as,   g_as);
    cudaGetSymbolAddress((void**)&ad,   g_ad);
    cudaGetSymbolAddress((void**)&deg,  g_deg);
    cudaGetSymbolAddress((void**)&cur,  g_cur);
    cudaGetSymbolAddress((void**)&off,  g_off);
    cudaGetSymbolAddress((void**)&csrc, g_csrc);
    cudaGetSymbolAddress((void**)&pool, g_pool);
    cudaGetSymbolAddress((void**)&cn,   g_cn);
    cudaGetSymbolAddress((void**)&c1,   g_c1);
    cudaGetSymbolAddress((void**)&c2,   g_c2);
    cudaGetSymbolAddress((void**)&xc,   g_xc);
    cudaGetSymbolAddress((void**)&f1,   g_f1);
    cudaGetSymbolAddress((void**)&f2,   g_f2);
    cudaGetSymbolAddress((void**)&f3,   g_f3);

    // two GNN branches -> xc[:, 0:128) and xc[:, 128:256)
    run_branch(x1, ei1, bt1, W1, aS1, aD1, b1, W2, aS2, aD2, b2, Wg, bg,
               h1, acc1, h2, as, ad, deg, cur, off, csrc, pool, xc);
    run_branch(x2, ei2, bt2, W1, aS1, aD1, b1, W2, aS2, aD2, b2, Wg, bg,
               h1, acc1, h2, as, ad, deg, cur, off, csrc, pool, xc + 128);

    // cell branch -> xc[:, 256:512)
    l2norm_k<<<N_GRAPH, 256>>>(cell, cn, FXT);
    gemm(cn, Wr1, br1, c1, N_GRAPH, 2048, FXT, 2048, 1);
    gemm(c1, Wr2, br2, c2, N_GRAPH, 512, 2048, 512, 1);
    gemm(c2, Wr3, br3, xc + 256, N_GRAPH, 256, 512, 512, 1);

    // fuse head
    l2norm_k<<<N_GRAPH, 256>>>(xc, xc, 512);
    gemm(xc, Wf1, bf1, f1, N_GRAPH, 1024, 512, 1024, 1);
    gemm(f1, Wf2, bf2, f2, N_GRAPH, 512, 1024, 512, 1);
    gemm(f2, Wf3, bf3, f3, N_GRAPH, 128, 512, 128, 1);
    gemm(f3, Wo, bo, out, N_GRAPH, 2, 128, 2, 0);
}

// round 12
// speedup vs baseline: 2.0750x; 1.0220x over previous
#include <cuda_runtime.h>
#include <math.h>
#include <stdint.h>

#define N_NODES 30000
#define N_EDGES 100000
#define EP      (N_EDGES + N_NODES)   // edges + self loops = 130000
#define N_GRAPH 1024
#define HEADS1  10
#define DCH     128
#define F1      1280                  // HEADS1 * DCH
#define FXD     78
#define FXT     954

// ---------------- scratch (device globals; no allocations allowed) ----------
__device__ float g_h1  [(size_t)N_NODES * F1];
__device__ float g_acc1[(size_t)N_NODES * F1];
__device__ float g_h2  [N_NODES * DCH];
__device__ float g_as  [N_NODES * HEADS1];
__device__ float g_ad  [N_NODES * HEADS1];
__device__ int   g_deg [N_NODES];
__device__ int   g_cur [N_NODES];
__device__ int   g_off [N_NODES + 1];
__device__ int   g_csrc[EP];
__device__ float g_pool[N_GRAPH * DCH];
__device__ float g_cn  [N_GRAPH * FXT];
__device__ float g_c1  [N_GRAPH * 2048];
__device__ float g_c2  [N_GRAPH * 512];
__device__ float g_xc  [N_GRAPH * 512];
__device__ float g_f1  [N_GRAPH * 1024];
__device__ float g_f2  [N_GRAPH * 512];
__device__ float g_f3  [N_GRAPH * 128];

// ---------------- helpers ----------------
__device__ __forceinline__ void atomicMaxF(float* a, float v) {
    if (v >= 0.f) atomicMax((int*)a, __float_as_int(v));
    else          atomicMin((unsigned int*)a, __float_as_uint(v));
}

__device__ __forceinline__ uint32_t f2tf32(float x) {
    uint32_t r;
    asm("cvt.rna.tf32.f32 %0, %1;" : "=r"(r) : "f"(x));
    return r;
}

__device__ __forceinline__ void mma_tf32(float c[4],
                                         uint32_t a0, uint32_t a1, uint32_t a2, uint32_t a3,
                                         uint32_t b0, uint32_t b1) {
    asm volatile("mma.sync.aligned.m16n8k8.row.col.f32.tf32.tf32.f32 "
                 "{%0,%1,%2,%3}, {%4,%5,%6,%7}, {%8,%9}, {%0,%1,%2,%3};"
                 : "+f"(c[0]), "+f"(c[1]), "+f"(c[2]), "+f"(c[3])
                 : "r"(a0), "r"(a1), "r"(a2), "r"(a3), "r"(b0), "r"(b1));
}

// ---------------- TF32 tensor-core GEMM, fragment-major SMEM + double buffer -
// C = act(A[M,K] @ B[K,N] + bias), A,B row-major, C stride ldc. act: 0 none, 1 relu.
// 128x128 block tile, 8 warps (2M x 4N), warp = 64x32 via 4x4 m16n8k8 MMAs.
// SMEM holds tf32 data pre-arranged in mma fragment order:
//   AF word:  ((kstep*8 + mtile)*32 + (lane ^ ((lane>>3)&3)))*4 + reg   (reg = a0..a3)
//   BF word:  (kstep*16 + ntile)*66 + lane*2 + reg                       (reg = b0..b1)
// so compute does 4x LDS.128 (A) + 4x LDS.64 (B) per k8-step instead of 24x LDS.32.
#define TM 128
#define TN 128
#define TK 16
#define AF_WORDS 2048     // 2 kstep * 8 mtile * 32 lanes * 4 regs
#define BF_WORDS 2112     // 2 kstep * 16 ntile * 66 words (64 + 2 pad)

__global__ __launch_bounds__(256, 2)
void gemm_k(const float* __restrict__ A, const float* __restrict__ B,
            const float* __restrict__ bias, float* __restrict__ C,
            int M, int N, int K, int ldc, int act)
{
    __shared__ uint32_t AF[2][AF_WORDS];
    __shared__ uint32_t BF[2][BF_WORDS];

    int tid  = threadIdx.x;
    int wid  = tid >> 5, lane = tid & 31;
    int g    = lane >> 2, tg = lane & 3;
    int warpM = wid >> 2, warpN = wid & 3;          // 2 x 4 warps
    int m0 = blockIdx.y * TM, n0 = blockIdx.x * TN;

    // ---- staging coords ----
    int ar     = tid >> 1;          // A tile row 0..127
    int mm     = ar & 15;           // row within 16-row mtile
    int mtileS = ar >> 4;           // 0..7
    int kstepA = tid & 1;           // this thread stages k (kstepA*8 .. +7)
    int br     = tid >> 5;          // B k row 0..7 (second pass +8)
    int bcq    = tid & 31;
    int ntileS = bcq >> 1;          // 0..15
    int nnb    = (bcq & 1) * 4;     // col base within ntile

    float a_reg[8];
    float4 b_reg[2];

    auto loadA = [&](int k0) {
        int gm = m0 + ar;
        int kb = k0 + kstepA * 8;
        if (gm < M) {
            const float* ap = A + (size_t)gm * K + kb;
            if (((K & 3) == 0) && (kb + 7 < K)) {
                float4 v0 = *(const float4*)(ap);
                float4 v1 = *(const float4*)(ap + 4);
                a_reg[0] = v0.x; a_reg[1] = v0.y; a_reg[2] = v0.z; a_reg[3] = v0.w;
                a_reg[4] = v1.x; a_reg[5] = v1.y; a_reg[6] = v1.z; a_reg[7] = v1.w;
            } else {
                #pragma unroll
                for (int j = 0; j < 8; j++) {
                    int gk = kb + j;
                    a_reg[j] = (gk < K) ? ap[j] : 0.f;
                }
            }
        } else {
            #pragma unroll
            for (int j = 0; j < 8; j++) a_reg[j] = 0.f;
        }
    };
    auto loadB = [&](int k0) {
        #pragma unroll
        for (int it = 0; it < 2; it++) {
            int gk = k0 + br + it * 8;
            int gn = n0 + ntileS * 8 + nnb;
            float4 v = make_float4(0.f, 0.f, 0.f, 0.f);
            if (gk < K) {
                const float* bp = B + (size_t)gk * N + gn;
                if (gn + 3 < N) v = *(const float4*)bp;
                else {
                    if (gn     < N) v.x = bp[0];
                    if (gn + 1 < N) v.y = bp[1];
                    if (gn + 2 < N) v.z = bp[2];
                }
            }
            b_reg[it] = v;
        }
    };
    auto storeA = [&](int buf) {
        uint32_t* dst = AF[buf] + (kstepA * 8 + mtileS) * 128;
        #pragma unroll
        for (int j = 0; j < 8; j++) {
            int lane_f = (mm & 7) * 4 + (j & 3);
            int reg    = (mm >> 3) + 2 * (j >> 2);
            int chunk  = lane_f ^ ((lane_f >> 3) & 3);
            dst[chunk * 4 + reg] = f2tf32(a_reg[j]);
        }
    };
    auto storeB = [&](int buf) {
        int kb3 = br & 3, regb = br >> 2;
        #pragma unroll
        for (int pass = 0; pass < 2; pass++) {
            uint32_t* dst = BF[buf] + (pass * 16 + ntileS) * 66;
            float vv[4] = { b_reg[pass].x, b_reg[pass].y, b_reg[pass].z, b_reg[pass].w };
            #pragma unroll
            for (int jj = 0; jj < 4; jj++) {
                int lane_b = (nnb + jj) * 4 + kb3;
                dst[lane_b * 2 + regb] = f2tf32(vv[jj]);
            }
        }
    };

    float acc[4][4][4] = {};
    int clane = lane ^ ((lane >> 3) & 3);

    auto compute = [&](int buf) {
        #pragma unroll
        for (int ks = 0; ks < 2; ks++) {
            uint4 af4[4];
            uint2 bf2[4];
            #pragma unroll
            for (int i = 0; i < 4; i++)
                af4[i] = *(const uint4*)&AF[buf][((ks * 8 + warpM * 4 + i) * 32 + clane) * 4];
            #pragma unroll
            for (int u = 0; u < 4; u++)
                bf2[u] = *(const uint2*)&BF[buf][(ks * 16 + warpN * 4 + u) * 66 + lane * 2];
            #pragma unroll
            for (int i = 0; i < 4; i++)
                #pragma unroll
                for (int u = 0; u < 4; u++)
                    mma_tf32(acc[i][u], af4[i].x, af4[i].y, af4[i].z, af4[i].w,
                             bf2[u].x, bf2[u].y);
        }
    };

    int nk = (K + TK - 1) / TK;
    loadA(0); loadB(0);
    storeA(0); storeB(0);
    __syncthreads();

    for (int t = 0; t < nk; t++) {
        int cb = t & 1;
        if (t + 1 < nk) { loadA((t + 1) * TK); loadB((t + 1) * TK); }
        compute(cb);
        if (t + 1 < nk) { storeA(cb ^ 1); storeB(cb ^ 1); __syncthreads(); }
    }

    // epilogue: c0,c1 -> (row, col..col+1), c2,c3 -> (row+8, ...)
    #pragma unroll
    for (int i = 0; i < 4; i++) {
        int mrow = m0 + warpM * 64 + i * 16 + g;
        #pragma unroll
        for (int u = 0; u < 4; u++) {
            int n = n0 + warpN * 32 + u * 8 + tg * 2;
            float b0 = 0.f, b1 = 0.f;
            if (bias) { if (n < N) b0 = bias[n]; if (n + 1 < N) b1 = bias[n + 1]; }
            #pragma unroll
            for (int half = 0; half < 2; half++) {
                int m = mrow + half * 8;
                if (m >= M) continue;
                float vx = acc[i][u][half * 2]     + b0;
                float vy = acc[i][u][half * 2 + 1] + b1;
                if (act == 1) { vx = fmaxf(vx, 0.f); vy = fmaxf(vy, 0.f); }
                if (n     < N) C[(size_t)m * ldc + n]     = vx;
                if (n + 1 < N) C[(size_t)m * ldc + n + 1] = vy;
            }
        }
    }
}

// ---------------- CSR build ----------------
__device__ __forceinline__ void edge_ends(int e, const int* __restrict__ ei,
                                          int& src, int& dst)
{
    if (e < N_EDGES) { src = ei[e]; dst = ei[N_EDGES + e]; }
    else             { src = dst = e - N_EDGES; }
}

__global__ void hist_k(const int* __restrict__ ei, int* __restrict__ deg) {
    int e = blockIdx.x * blockDim.x + threadIdx.x;
    if (e >= EP) return;
    int src, dst; edge_ends(e, ei, src, dst);
    (void)src;
    atomicAdd(&deg[dst], 1);
}

// single-block exclusive scan over N_NODES ints -> off[0..N_NODES]
__global__ void scan_k(const int* __restrict__ deg, int* __restrict__ off) {
    __shared__ int sm[1024];
    __shared__ int carry;
    if (threadIdx.x == 0) { carry = 0; off[0] = 0; }
    __syncthreads();
    for (int base = 0; base < N_NODES; base += 1024) {
        int i = base + threadIdx.x;
        int v = (i < N_NODES) ? deg[i] : 0;
        sm[threadIdx.x] = v;
        __syncthreads();
        #pragma unroll
        for (int s = 1; s < 1024; s <<= 1) {
            int t = (threadIdx.x >= s) ? sm[threadIdx.x - s] : 0;
            __syncthreads();
            sm[threadIdx.x] += t;
            __syncthreads();
        }
        if (i < N_NODES) off[i + 1] = carry + sm[threadIdx.x];
        __syncthreads();
        if (threadIdx.x == 0) carry += sm[1023];
        __syncthreads();
    }
}

__global__ void scatter_k(const int* __restrict__ ei, const int* __restrict__ off,
                          int* __restrict__ cur, int* __restrict__ csrc) {
    int e = blockIdx.x * blockDim.x + threadIdx.x;
    if (e >= EP) return;
    int src, dst; edge_ends(e, ei, src, dst);
    int pos = off[dst] + atomicAdd(&cur[dst], 1);
    csrc[pos] = src;
}

// ---------------- fused GAT softmax-aggregate ----------------
// warp per (node, head): out[n,hd,:] = elu( sum_e ex_e * h[src_e,hd,:] / sum_e ex_e + bias )
__global__ void gat_aggr_k(const int* __restrict__ off, const int* __restrict__ csrc,
                           const float* __restrict__ as, const float* __restrict__ ad,
                           const float* __restrict__ h, const float* __restrict__ bias,
                           float* __restrict__ outbuf, int heads)
{
    int w = (blockIdx.x * blockDim.x + threadIdx.x) >> 5;
    int lane = threadIdx.x & 31;
    if (w >= N_NODES * heads) return;
    int n = w / heads, hd = w - n * heads;
    int r0 = off[n], r1 = off[n + 1];
    float adn = ad[n * heads + hd];
    float4 acc = make_float4(0.f, 0.f, 0.f, 0.f);
    float den = 0.f;
    for (int e = r0; e < r1; e++) {
        int src = csrc[e];
        float v = as[src * heads + hd] + adn;
        v = v > 0.f ? v : 0.2f * v;
        float ex = __expf(v);
        den += ex;
        const float4 hv = *(const float4*)(h + ((size_t)src * heads + hd) * DCH + lane * 4);
        acc.x += ex * hv.x; acc.y += ex * hv.y; acc.z += ex * hv.z; acc.w += ex * hv.w;
    }
    float inv = 1.f / (den + 1e-16f);
    const float4 bb = *(const float4*)(bias + hd * DCH + lane * 4);
    float o0 = acc.x * inv + bb.x, o1 = acc.y * inv + bb.y;
    float o2 = acc.z * inv + bb.z, o3 = acc.w * inv + bb.w;
    o0 = o0 > 0.f ? o0 : __expf(o0) - 1.f;
    o1 = o1 > 0.f ? o1 : __expf(o1) - 1.f;
    o2 = o2 > 0.f ? o2 : __expf(o2) - 1.f;
    o3 = o3 > 0.f ? o3 : __expf(o3) - 1.f;
    *(float4*)(outbuf + ((size_t)n * heads + hd) * DCH + lane * 4) =
        make_float4(o0, o1, o2, o3);
}

// layer-2 variant (heads=1) fused with global max pool
__global__ void gat_aggr_pool_k(const int* __restrict__ off, const int* __restrict__ csrc,
                                const float* __restrict__ as, const float* __restrict__ ad,
                                const float* __restrict__ h, const float* __restrict__ bias,
                                const int* __restrict__ batch, float* __restrict__ pool)
{
    int n = (blockIdx.x * blockDim.x + threadIdx.x) >> 5;
    int lane = threadIdx.x & 31;
    if (n >= N_NODES) return;
    int r0 = off[n], r1 = off[n + 1];
    float adn = ad[n];
    float4 acc = make_float4(0.f, 0.f, 0.f, 0.f);
    float den = 0.f;
    for (int e = r0; e < r1; e++) {
        int src = csrc[e];
        float v = as[src] + adn;
        v = v > 0.f ? v : 0.2f * v;
        float ex = __expf(v);
        den += ex;
        const float4 hv = *(const float4*)(h + (size_t)src * DCH + lane * 4);
        acc.x += ex * hv.x; acc.y += ex * hv.y; acc.z += ex * hv.z; acc.w += ex * hv.w;
    }
    float inv = 1.f / (den + 1e-16f);
    const float4 bb = *(const float4*)(bias + lane * 4);
    float o[4];
    o[0] = acc.x * inv + bb.x; o[1] = acc.y * inv + bb.y;
    o[2] = acc.z * inv + bb.z; o[3] = acc.w * inv + bb.w;
    float* pp = pool + (size_t)batch[n] * DCH + lane * 4;
    #pragma unroll
    for (int j = 0; j < 4; j++) {
        float v = o[j] > 0.f ? o[j] : __expf(o[j]) - 1.f;
        atomicMaxF(pp + j, v);
    }
}

// ---------------- elementwise ----------------
__global__ void fill4_k(float4* __restrict__ p, float v, int n4) {
    int t = blockIdx.x * blockDim.x + threadIdx.x;
    if (t < n4) p[t] = make_float4(v, v, v, v);
}

__global__ void alpha_k(const float* __restrict__ h,
                        const float* __restrict__ a_s, const float* __restrict__ a_d,
                        float* __restrict__ os, float* __restrict__ od,
                        int n, int heads)
{
    int t = blockIdx.x * blockDim.x + threadIdx.x;
    if (t >= n * heads) return;
    int hd = t % heads;
    const float* hp = h + (size_t)t * DCH;
    const float* sp = a_s + hd * DCH;
    const float* dp = a_d + hd * DCH;
    float s1 = 0.f, s2 = 0.f;
    #pragma unroll 8
    for (int c = 0; c < DCH; c += 4) {
        float4 hv = *(const float4*)(hp + c);
        float4 sv = *(const float4*)(sp + c);
        float4 dv = *(const float4*)(dp + c);
        s1 += hv.x * sv.x + hv.y * sv.y + hv.z * sv.z + hv.w * sv.w;
        s2 += hv.x * dv.x + hv.y * dv.y + hv.z * dv.z + hv.w * dv.w;
    }
    os[t] = s1;
    od[t] = s2;
}

// row-wise L2 normalize (block per row); safe in-place
__global__ void l2norm_k(const float* __restrict__ in, float* __restrict__ out, int cols)
{
    __shared__ float red[256];
    int row = blockIdx.x;
    const float* ip = in + (size_t)row * cols;
    float s = 0.f;
    for (int c = threadIdx.x; c < cols; c += 256) { float v = ip[c]; s += v * v; }
    red[threadIdx.x] = s;
    __syncthreads();
    for (int off = 128; off > 0; off >>= 1) {
        if (threadIdx.x < off) red[threadIdx.x] += red[threadIdx.x + off];
        __syncthreads();
    }
    float sc = 1.f / fmaxf(sqrtf(red[0]), 1e-12f);
    float* op = out + (size_t)row * cols;
    for (int c = threadIdx.x; c < cols; c += 256) op[c] = ip[c] * sc;
}

// ---------------- host orchestration ----------------
static void gemm(const float* A, const float* B, const float* bias, float* C,
                 int M, int N, int K, int ldc, int act)
{
    dim3 grid((N + TN - 1) / TN, (M + TM - 1) / TM);
    gemm_k<<<grid, 256>>>(A, B, bias, C, M, N, K, ldc, act);
}

static void run_branch(const float* x, const int* ei, const int* batch,
                       const float* W1, const float* a_s1, const float* a_d1, const float* b1,
                       const float* W2, const float* a_s2, const float* a_d2, const float* b2,
                       const float* Wg, const float* bg,
                       float* h1, float* acc1, float* h2,
                       float* as, float* ad,
                       int* deg, int* cur, int* off, int* csrc,
                       float* pool, float* vout)
{
    const int T = 256;
    // --- CSR build (shared by both layers) ---
    cudaMemsetAsync(deg, 0, N_NODES * 4);
    cudaMemsetAsync(cur, 0, N_NODES * 4);
    hist_k<<<(EP + T - 1) / T, T>>>(ei, deg);
    scan_k<<<1, 1024>>>(deg, off);
    scatter_k<<<(EP + T - 1) / T, T>>>(ei, off, cur, csrc);

    // --- GATConv1 (H=10, D=128) ---
    gemm(x, W1, nullptr, h1, N_NODES, F1, FXD, F1, 0);
    alpha_k<<<(N_NODES * HEADS1 + T - 1) / T, T>>>(h1, a_s1, a_d1, as, ad, N_NODES, HEADS1);
    gat_aggr_k<<<((size_t)N_NODES * HEADS1 * 32 + T - 1) / T, T>>>(off, csrc, as, ad, h1, b1,
                                                                   acc1, HEADS1);

    // --- GATConv2 (H=1, D=128) + fused max pool ---
    gemm(acc1, W2, nullptr, h2, N_NODES, DCH, F1, DCH, 0);
    alpha_k<<<(N_NODES + T - 1) / T, T>>>(h2, a_s2, a_d2, as, ad, N_NODES, 1);
    fill4_k<<<(N_GRAPH * DCH / 4 + T - 1) / T, T>>>((float4*)pool, -INFINITY, N_GRAPH * DCH / 4);
    gat_aggr_pool_k<<<((size_t)N_NODES * 32 + T - 1) / T, T>>>(off, csrc, as, ad, h2, b2,
                                                               batch, pool);
    gemm(pool, Wg, bg, vout, N_GRAPH, DCH, DCH, 512, 1);   // relu, strided into concat buf
}

extern "C" void kernel_launch(void* const* d_in, const int* in_sizes, int n_in,
                              void* d_out, int out_size)
{
    const float* x1   = (const float*)d_in[0];
    const int*   ei1  = (const int*)  d_in[1];
    const int*   bt1  = (const int*)  d_in[2];
    const float* x2   = (const float*)d_in[3];
    const int*   ei2  = (const int*)  d_in[4];
    const int*   bt2  = (const int*)  d_in[5];
    const float* cell = (const float*)d_in[6];
    const float* W1   = (const float*)d_in[7];
    const float* aS1  = (const float*)d_in[8];
    const float* aD1  = (const float*)d_in[9];
    const float* b1   = (const float*)d_in[10];
    const float* W2   = (const float*)d_in[11];
    const float* aS2  = (const float*)d_in[12];
    const float* aD2  = (const float*)d_in[13];
    const float* b2   = (const float*)d_in[14];
    const float* Wg   = (const float*)d_in[15];
    const float* bg   = (const float*)d_in[16];
    const float* Wr1  = (const float*)d_in[17];
    const float* br1  = (const float*)d_in[18];
    const float* Wr2  = (const float*)d_in[19];
    const float* br2  = (const float*)d_in[20];
    const float* Wr3  = (const float*)d_in[21];
    const float* br3  = (const float*)d_in[22];
    const float* Wf1  = (const float*)d_in[23];
    const float* bf1  = (const float*)d_in[24];
    const float* Wf2  = (const float*)d_in[25];
    const float* bf2  = (const float*)d_in[26];
    const float* Wf3  = (const float*)d_in[27];
    const float* bf3  = (const float*)d_in[28];
    const float* Wo   = (const float*)d_in[29];
    const float* bo   = (const float*)d_in[30];
    float* out = (float*)d_out;

    float *h1, *acc1, *h2, *as, *ad, *pool;
    float *cn, *c1, *c2, *xc, *f1, *f2, *f3;
    int *deg, *cur, *off, *csrc;
    cudaGetSymbolAddress((void**)&h1,   g_h1);
    cudaGetSymbolAddress((void**)&acc1, g_acc1);
    cudaGetSymbolAddress((void**)&h2,   g_h2);
    cudaGetSymbolAddress((void**)&as,   g_as);
    cudaGetSymbolAddress((void**)&ad,   g_ad);
    cudaGetSymbolAddress((void**)&deg,  g_deg);
    cudaGetSymbolAddress((void**)&cur,  g_cur);
    cudaGetSymbolAddress((void**)&off,  g_off);
    cudaGetSymbolAddress((void**)&csrc, g_csrc);
    cudaGetSymbolAddress((void**)&pool, g_pool);
    cudaGetSymbolAddress((void**)&cn,   g_cn);
    cudaGetSymbolAddress((void**)&c1,   g_c1);
    cudaGetSymbolAddress((void**)&c2,   g_c2);
    cudaGetSymbolAddress((void**)&xc,   g_xc);
    cudaGetSymbolAddress((void**)&f1,   g_f1);
    cudaGetSymbolAddress((void**)&f2,   g_f2);
    cudaGetSymbolAddress((void**)&f3,   g_f3);

    // two GNN branches -> xc[:, 0:128) and xc[:, 128:256)
    run_branch(x1, ei1, bt1, W1, aS1, aD1, b1, W2, aS2, aD2, b2, Wg, bg,
               h1, acc1, h2, as, ad, deg, cur, off, csrc, pool, xc);
    run_branch(x2, ei2, bt2, W1, aS1, aD1, b1, W2, aS2, aD2, b2, Wg, bg,
               h1, acc1, h2, as, ad, deg, cur, off, csrc, pool, xc + 128);

    // cell branch -> xc[:, 256:512)
    l2norm_k<<<N_GRAPH, 256>>>(cell, cn, FXT);
    gemm(cn, Wr1, br1, c1, N_GRAPH, 2048, FXT, 2048, 1);
    gemm(c1, Wr2, br2, c2, N_GRAPH, 512, 2048, 512, 1);
    gemm(c2, Wr3, br3, xc + 256, N_GRAPH, 256, 512, 512, 1);

    // fuse head
    l2norm_k<<<N_GRAPH, 256>>>(xc, xc, 512);
    gemm(xc, Wf1, bf1, f1, N_GRAPH, 1024, 512, 1024, 1);
    gemm(f1, Wf2, bf2, f2, N_GRAPH, 512, 1024, 512, 1);
    gemm(f2, Wf3, bf3, f3, N_GRAPH, 128, 512, 128, 1);
    gemm(f3, Wo, bo, out, N_GRAPH, 2, 128, 2, 0);
}

// round 13
// speedup vs baseline: 2.5886x; 1.2475x over previous
#include <cuda_runtime.h>
#include <math.h>
#include <stdint.h>

#define N_NODES 30000
#define N_EDGES 100000
#define EP      (N_EDGES + N_NODES)   // edges + self loops = 130000
#define N_GRAPH 1024
#define HEADS1  10
#define DCH     128
#define F1      1280                  // HEADS1 * DCH
#define FXD     78
#define FXT     954

// ---------------- scratch (device globals; no allocations allowed) ----------
// branch 1
__device__ float g_h1  [(size_t)N_NODES * F1];
__device__ float g_acc1[(size_t)N_NODES * F1];
__device__ float g_h2  [N_NODES * DCH];
__device__ float g_as  [N_NODES * HEADS1];
__device__ float g_ad  [N_NODES * HEADS1];
__device__ int   g_deg [N_NODES];
__device__ int   g_cur [N_NODES];
__device__ int   g_off [N_NODES + 1];
__device__ int   g_csrc[EP];
__device__ float g_pool[N_GRAPH * DCH];
// branch 2 (parallel execution -> fully separate scratch)
__device__ float g_h1B  [(size_t)N_NODES * F1];
__device__ float g_acc1B[(size_t)N_NODES * F1];
__device__ float g_h2B  [N_NODES * DCH];
__device__ float g_asB  [N_NODES * HEADS1];
__device__ float g_adB  [N_NODES * HEADS1];
__device__ int   g_degB [N_NODES];
__device__ int   g_curB [N_NODES];
__device__ int   g_offB [N_NODES + 1];
__device__ int   g_csrcB[EP];
__device__ float g_poolB[N_GRAPH * DCH];
// cell + head
__device__ float g_cn  [N_GRAPH * FXT];
__device__ float g_c1  [N_GRAPH * 2048];
__device__ float g_c2  [N_GRAPH * 512];
__device__ float g_xc  [N_GRAPH * 512];
__device__ float g_f1  [N_GRAPH * 1024];
__device__ float g_f2  [N_GRAPH * 512];
__device__ float g_f3  [N_GRAPH * 128];

// ---------------- helpers ----------------
__device__ __forceinline__ void atomicMaxF(float* a, float v) {
    if (v >= 0.f) atomicMax((int*)a, __float_as_int(v));
    else          atomicMin((unsigned int*)a, __float_as_uint(v));
}

__device__ __forceinline__ uint32_t f2tf32(float x) {
    uint32_t r;
    asm("cvt.rna.tf32.f32 %0, %1;" : "=r"(r) : "f"(x));
    return r;
}

__device__ __forceinline__ void mma_tf32(float c[4],
                                         uint32_t a0, uint32_t a1, uint32_t a2, uint32_t a3,
                                         uint32_t b0, uint32_t b1) {
    asm volatile("mma.sync.aligned.m16n8k8.row.col.f32.tf32.tf32.f32 "
                 "{%0,%1,%2,%3}, {%4,%5,%6,%7}, {%8,%9}, {%0,%1,%2,%3};"
                 : "+f"(c[0]), "+f"(c[1]), "+f"(c[2]), "+f"(c[3])
                 : "r"(a0), "r"(a1), "r"(a2), "r"(a3), "r"(b0), "r"(b1));
}

// ---------------- TF32 tensor-core GEMM (fragment-major SMEM, double buffer) -
#define TM 128
#define TN 128
#define TK 16
#define AF_WORDS 2048
#define BF_WORDS 2112

__global__ __launch_bounds__(256, 2)
void gemm_k(const float* __restrict__ A, const float* __restrict__ B,
            const float* __restrict__ bias, float* __restrict__ C,
            int M, int N, int K, int ldc, int act)
{
    __shared__ uint32_t AF[2][AF_WORDS];
    __shared__ uint32_t BF[2][BF_WORDS];

    int tid  = threadIdx.x;
    int wid  = tid >> 5, lane = tid & 31;
    int g    = lane >> 2, tg = lane & 3;
    int warpM = wid >> 2, warpN = wid & 3;
    int m0 = blockIdx.y * TM, n0 = blockIdx.x * TN;

    int ar     = tid >> 1;
    int mm     = ar & 15;
    int mtileS = ar >> 4;
    int kstepA = tid & 1;
    int br     = tid >> 5;
    int bcq    = tid & 31;
    int ntileS = bcq >> 1;
    int nnb    = (bcq & 1) * 4;

    float a_reg[8];
    float4 b_reg[2];

    auto loadA = [&](int k0) {
        int gm = m0 + ar;
        int kb = k0 + kstepA * 8;
        if (gm < M) {
            const float* ap = A + (size_t)gm * K + kb;
            if (((K & 3) == 0) && (kb + 7 < K)) {
                float4 v0 = *(const float4*)(ap);
                float4 v1 = *(const float4*)(ap + 4);
                a_reg[0] = v0.x; a_reg[1] = v0.y; a_reg[2] = v0.z; a_reg[3] = v0.w;
                a_reg[4] = v1.x; a_reg[5] = v1.y; a_reg[6] = v1.z; a_reg[7] = v1.w;
            } else {
                #pragma unroll
                for (int j = 0; j < 8; j++) {
                    int gk = kb + j;
                    a_reg[j] = (gk < K) ? ap[j] : 0.f;
                }
            }
        } else {
            #pragma unroll
            for (int j = 0; j < 8; j++) a_reg[j] = 0.f;
        }
    };
    auto loadB = [&](int k0) {
        #pragma unroll
        for (int it = 0; it < 2; it++) {
            int gk = k0 + br + it * 8;
            int gn = n0 + ntileS * 8 + nnb;
            float4 v = make_float4(0.f, 0.f, 0.f, 0.f);
            if (gk < K) {
                const float* bp = B + (size_t)gk * N + gn;
                if (gn + 3 < N) v = *(const float4*)bp;
                else {
                    if (gn     < N) v.x = bp[0];
                    if (gn + 1 < N) v.y = bp[1];
                    if (gn + 2 < N) v.z = bp[2];
                }
            }
            b_reg[it] = v;
        }
    };
    auto storeA = [&](int buf) {
        uint32_t* dst = AF[buf] + (kstepA * 8 + mtileS) * 128;
        #pragma unroll
        for (int j = 0; j < 8; j++) {
            int lane_f = (mm & 7) * 4 + (j & 3);
            int reg    = (mm >> 3) + 2 * (j >> 2);
            int chunk  = lane_f ^ ((lane_f >> 3) & 3);
            dst[chunk * 4 + reg] = f2tf32(a_reg[j]);
        }
    };
    auto storeB = [&](int buf) {
        int kb3 = br & 3, regb = br >> 2;
        #pragma unroll
        for (int pass = 0; pass < 2; pass++) {
            uint32_t* dst = BF[buf] + (pass * 16 + ntileS) * 66;
            float vv[4] = { b_reg[pass].x, b_reg[pass].y, b_reg[pass].z, b_reg[pass].w };
            #pragma unroll
            for (int jj = 0; jj < 4; jj++) {
                int lane_b = (nnb + jj) * 4 + kb3;
                dst[lane_b * 2 + regb] = f2tf32(vv[jj]);
            }
        }
    };

    float acc[4][4][4] = {};
    int clane = lane ^ ((lane >> 3) & 3);

    auto compute = [&](int buf) {
        #pragma unroll
        for (int ks = 0; ks < 2; ks++) {
            uint4 af4[4];
            uint2 bf2[4];
            #pragma unroll
            for (int i = 0; i < 4; i++)
                af4[i] = *(const uint4*)&AF[buf][((ks * 8 + warpM * 4 + i) * 32 + clane) * 4];
            #pragma unroll
            for (int u = 0; u < 4; u++)
                bf2[u] = *(const uint2*)&BF[buf][(ks * 16 + warpN * 4 + u) * 66 + lane * 2];
            #pragma unroll
            for (int i = 0; i < 4; i++)
                #pragma unroll
                for (int u = 0; u < 4; u++)
                    mma_tf32(acc[i][u], af4[i].x, af4[i].y, af4[i].z, af4[i].w,
                             bf2[u].x, bf2[u].y);
        }
    };

    int nk = (K + TK - 1) / TK;
    loadA(0); loadB(0);
    storeA(0); storeB(0);
    __syncthreads();

    for (int t = 0; t < nk; t++) {
        int cb = t & 1;
        if (t + 1 < nk) { loadA((t + 1) * TK); loadB((t + 1) * TK); }
        compute(cb);
        if (t + 1 < nk) { storeA(cb ^ 1); storeB(cb ^ 1); __syncthreads(); }
    }

    #pragma unroll
    for (int i = 0; i < 4; i++) {
        int mrow = m0 + warpM * 64 + i * 16 + g;
        #pragma unroll
        for (int u = 0; u < 4; u++) {
            int n = n0 + warpN * 32 + u * 8 + tg * 2;
            float b0 = 0.f, b1 = 0.f;
            if (bias) { if (n < N) b0 = bias[n]; if (n + 1 < N) b1 = bias[n + 1]; }
            #pragma unroll
            for (int half = 0; half < 2; half++) {
                int m = mrow + half * 8;
                if (m >= M) continue;
                float vx = acc[i][u][half * 2]     + b0;
                float vy = acc[i][u][half * 2 + 1] + b1;
                if (act == 1) { vx = fmaxf(vx, 0.f); vy = fmaxf(vy, 0.f); }
                if (n     < N) C[(size_t)m * ldc + n]     = vx;
                if (n + 1 < N) C[(size_t)m * ldc + n + 1] = vy;
            }
        }
    }
}

// ---------------- CSR build ----------------
__device__ __forceinline__ void edge_ends(int e, const int* __restrict__ ei,
                                          int& src, int& dst)
{
    if (e < N_EDGES) { src = ei[e]; dst = ei[N_EDGES + e]; }
    else             { src = dst = e - N_EDGES; }
}

__global__ void hist_k(const int* __restrict__ ei, int* __restrict__ deg) {
    int e = blockIdx.x * blockDim.x + threadIdx.x;
    if (e >= EP) return;
    int src, dst; edge_ends(e, ei, src, dst);
    (void)src;
    atomicAdd(&deg[dst], 1);
}

// single-block exclusive scan over N_NODES ints -> off[0..N_NODES]
__global__ void scan_k(const int* __restrict__ deg, int* __restrict__ off) {
    __shared__ int sm[1024];
    __shared__ int carry;
    if (threadIdx.x == 0) { carry = 0; off[0] = 0; }
    __syncthreads();
    for (int base = 0; base < N_NODES; base += 1024) {
        int i = base + threadIdx.x;
        int v = (i < N_NODES) ? deg[i] : 0;
        sm[threadIdx.x] = v;
        __syncthreads();
        #pragma unroll
        for (int s = 1; s < 1024; s <<= 1) {
            int t = (threadIdx.x >= s) ? sm[threadIdx.x - s] : 0;
            __syncthreads();
            sm[threadIdx.x] += t;
            __syncthreads();
        }
        if (i < N_NODES) off[i + 1] = carry + sm[threadIdx.x];
        __syncthreads();
        if (threadIdx.x == 0) carry += sm[1023];
        __syncthreads();
    }
}

__global__ void scatter_k(const int* __restrict__ ei, const int* __restrict__ off,
                          int* __restrict__ cur, int* __restrict__ csrc) {
    int e = blockIdx.x * blockDim.x + threadIdx.x;
    if (e >= EP) return;
    int src, dst; edge_ends(e, ei, src, dst);
    int pos = off[dst] + atomicAdd(&cur[dst], 1);
    csrc[pos] = src;
}

// ---------------- fused GAT softmax-aggregate ----------------
__global__ void gat_aggr_k(const int* __restrict__ off, const int* __restrict__ csrc,
                           const float* __restrict__ as, const float* __restrict__ ad,
                           const float* __restrict__ h, const float* __restrict__ bias,
                           float* __restrict__ outbuf, int heads)
{
    int w = (blockIdx.x * blockDim.x + threadIdx.x) >> 5;
    int lane = threadIdx.x & 31;
    if (w >= N_NODES * heads) return;
    int n = w / heads, hd = w - n * heads;
    int r0 = off[n], r1 = off[n + 1];
    float adn = ad[n * heads + hd];
    float4 acc = make_float4(0.f, 0.f, 0.f, 0.f);
    float den = 0.f;
    for (int e = r0; e < r1; e++) {
        int src = csrc[e];
        float v = as[src * heads + hd] + adn;
        v = v > 0.f ? v : 0.2f * v;
        float ex = __expf(v);
        den += ex;
        const float4 hv = *(const float4*)(h + ((size_t)src * heads + hd) * DCH + lane * 4);
        acc.x += ex * hv.x; acc.y += ex * hv.y; acc.z += ex * hv.z; acc.w += ex * hv.w;
    }
    float inv = 1.f / (den + 1e-16f);
    const float4 bb = *(const float4*)(bias + hd * DCH + lane * 4);
    float o0 = acc.x * inv + bb.x, o1 = acc.y * inv + bb.y;
    float o2 = acc.z * inv + bb.z, o3 = acc.w * inv + bb.w;
    o0 = o0 > 0.f ? o0 : __expf(o0) - 1.f;
    o1 = o1 > 0.f ? o1 : __expf(o1) - 1.f;
    o2 = o2 > 0.f ? o2 : __expf(o2) - 1.f;
    o3 = o3 > 0.f ? o3 : __expf(o3) - 1.f;
    *(float4*)(outbuf + ((size_t)n * heads + hd) * DCH + lane * 4) =
        make_float4(o0, o1, o2, o3);
}

__global__ void gat_aggr_pool_k(const int* __restrict__ off, const int* __restrict__ csrc,
                                const float* __restrict__ as, const float* __restrict__ ad,
                                const float* __restrict__ h, const float* __restrict__ bias,
                                const int* __restrict__ batch, float* __restrict__ pool)
{
    int n = (blockIdx.x * blockDim.x + threadIdx.x) >> 5;
    int lane = threadIdx.x & 31;
    if (n >= N_NODES) return;
    int r0 = off[n], r1 = off[n + 1];
    float adn = ad[n];
    float4 acc = make_float4(0.f, 0.f, 0.f, 0.f);
    float den = 0.f;
    for (int e = r0; e < r1; e++) {
        int src = csrc[e];
        float v = as[src] + adn;
        v = v > 0.f ? v : 0.2f * v;
        float ex = __expf(v);
        den += ex;
        const float4 hv = *(const float4*)(h + (size_t)src * DCH + lane * 4);
        acc.x += ex * hv.x; acc.y += ex * hv.y; acc.z += ex * hv.z; acc.w += ex * hv.w;
    }
    float inv = 1.f / (den + 1e-16f);
    const float4 bb = *(const float4*)(bias + lane * 4);
    float o[4];
    o[0] = acc.x * inv + bb.x; o[1] = acc.y * inv + bb.y;
    o[2] = acc.z * inv + bb.z; o[3] = acc.w * inv + bb.w;
    float* pp = pool + (size_t)batch[n] * DCH + lane * 4;
    #pragma unroll
    for (int j = 0; j < 4; j++) {
        float v = o[j] > 0.f ? o[j] : __expf(o[j]) - 1.f;
        atomicMaxF(pp + j, v);
    }
}

// ---------------- elementwise ----------------
__global__ void fill4_k(float4* __restrict__ p, float v, int n4) {
    int t = blockIdx.x * blockDim.x + threadIdx.x;
    if (t < n4) p[t] = make_float4(v, v, v, v);
}

__global__ void alpha_k(const float* __restrict__ h,
                        const float* __restrict__ a_s, const float* __restrict__ a_d,
                        float* __restrict__ os, float* __restrict__ od,
                        int n, int heads)
{
    int t = blockIdx.x * blockDim.x + threadIdx.x;
    if (t >= n * heads) return;
    int hd = t % heads;
    const float* hp = h + (size_t)t * DCH;
    const float* sp = a_s + hd * DCH;
    const float* dp = a_d + hd * DCH;
    float s1 = 0.f, s2 = 0.f;
    #pragma unroll 8
    for (int c = 0; c < DCH; c += 4) {
        float4 hv = *(const float4*)(hp + c);
        float4 sv = *(const float4*)(sp + c);
        float4 dv = *(const float4*)(dp + c);
        s1 += hv.x * sv.x + hv.y * sv.y + hv.z * sv.z + hv.w * sv.w;
        s2 += hv.x * dv.x + hv.y * dv.y + hv.z * dv.z + hv.w * dv.w;
    }
    os[t] = s1;
    od[t] = s2;
}

__global__ void l2norm_k(const float* __restrict__ in, float* __restrict__ out, int cols)
{
    __shared__ float red[256];
    int row = blockIdx.x;
    const float* ip = in + (size_t)row * cols;
    float s = 0.f;
    for (int c = threadIdx.x; c < cols; c += 256) { float v = ip[c]; s += v * v; }
    red[threadIdx.x] = s;
    __syncthreads();
    for (int off = 128; off > 0; off >>= 1) {
        if (threadIdx.x < off) red[threadIdx.x] += red[threadIdx.x + off];
        __syncthreads();
    }
    float sc = 1.f / fmaxf(sqrtf(red[0]), 1e-12f);
    float* op = out + (size_t)row * cols;
    for (int c = threadIdx.x; c < cols; c += 256) op[c] = ip[c] * sc;
}

// ---------------- host orchestration ----------------
static void gemm(cudaStream_t st, const float* A, const float* B, const float* bias,
                 float* C, int M, int N, int K, int ldc, int act)
{
    dim3 grid((N + TN - 1) / TN, (M + TM - 1) / TM);
    gemm_k<<<grid, 256, 0, st>>>(A, B, bias, C, M, N, K, ldc, act);
}

static void run_branch(cudaStream_t st,
                       const float* x, const int* ei, const int* batch,
                       const float* W1, const float* a_s1, const float* a_d1, const float* b1,
                       const float* W2, const float* a_s2, const float* a_d2, const float* b2,
                       const float* Wg, const float* bg,
                       float* h1, float* acc1, float* h2,
                       float* as, float* ad,
                       int* deg, int* cur, int* off, int* csrc,
                       float* pool, float* vout)
{
    const int T = 256;
    // --- CSR build (shared by both layers) ---
    cudaMemsetAsync(deg, 0, N_NODES * 4, st);
    cudaMemsetAsync(cur, 0, N_NODES * 4, st);
    hist_k<<<(EP + T - 1) / T, T, 0, st>>>(ei, deg);
    scan_k<<<1, 1024, 0, st>>>(deg, off);
    scatter_k<<<(EP + T - 1) / T, T, 0, st>>>(ei, off, cur, csrc);

    // --- GATConv1 (H=10, D=128) ---
    gemm(st, x, W1, nullptr, h1, N_NODES, F1, FXD, F1, 0);
    alpha_k<<<(N_NODES * HEADS1 + T - 1) / T, T, 0, st>>>(h1, a_s1, a_d1, as, ad,
                                                          N_NODES, HEADS1);
    gat_aggr_k<<<((size_t)N_NODES * HEADS1 * 32 + T - 1) / T, T, 0, st>>>(
        off, csrc, as, ad, h1, b1, acc1, HEADS1);

    // --- GATConv2 (H=1, D=128) + fused max pool ---
    gemm(st, acc1, W2, nullptr, h2, N_NODES, DCH, F1, DCH, 0);
    alpha_k<<<(N_NODES + T - 1) / T, T, 0, st>>>(h2, a_s2, a_d2, as, ad, N_NODES, 1);
    fill4_k<<<(N_GRAPH * DCH / 4 + T - 1) / T, T, 0, st>>>((float4*)pool, -INFINITY,
                                                           N_GRAPH * DCH / 4);
    gat_aggr_pool_k<<<((size_t)N_NODES * 32 + T - 1) / T, T, 0, st>>>(
        off, csrc, as, ad, h2, b2, batch, pool);
    gemm(st, pool, Wg, bg, vout, N_GRAPH, DCH, DCH, 512, 1);
}

extern "C" void kernel_launch(void* const* d_in, const int* in_sizes, int n_in,
                              void* d_out, int out_size)
{
    const float* x1   = (const float*)d_in[0];
    const int*   ei1  = (const int*)  d_in[1];
    const int*   bt1  = (const int*)  d_in[2];
    const float* x2   = (const float*)d_in[3];
    const int*   ei2  = (const int*)  d_in[4];
    const int*   bt2  = (const int*)  d_in[5];
    const float* cell = (const float*)d_in[6];
    const float* W1   = (const float*)d_in[7];
    const float* aS1  = (const float*)d_in[8];
    const float* aD1  = (const float*)d_in[9];
    const float* b1   = (const float*)d_in[10];
    const float* W2   = (const float*)d_in[11];
    const float* aS2  = (const float*)d_in[12];
    const float* aD2  = (const float*)d_in[13];
    const float* b2   = (const float*)d_in[14];
    const float* Wg   = (const float*)d_in[15];
    const float* bg   = (const float*)d_in[16];
    const float* Wr1  = (const float*)d_in[17];
    const float* br1  = (const float*)d_in[18];
    const float* Wr2  = (const float*)d_in[19];
    const float* br2  = (const float*)d_in[20];
    const float* Wr3  = (const float*)d_in[21];
    const float* br3  = (const float*)d_in[22];
    const float* Wf1  = (const float*)d_in[23];
    const float* bf1  = (const float*)d_in[24];
    const float* Wf2  = (const float*)d_in[25];
    const float* bf2  = (const float*)d_in[26];
    const float* Wf3  = (const float*)d_in[27];
    const float* bf3  = (const float*)d_in[28];
    const float* Wo   = (const float*)d_in[29];
    const float* bo   = (const float*)d_in[30];
    float* out = (float*)d_out;

    float *h1, *acc1, *h2, *as, *ad, *pool;
    float *h1B, *acc1B, *h2B, *asB, *adB, *poolB;
    float *cn, *c1, *c2, *xc, *f1, *f2, *f3;
    int *deg, *cur, *off, *csrc, *degB, *curB, *offB, *csrcB;
    cudaGetSymbolAddress((void**)&h1,    g_h1);
    cudaGetSymbolAddress((void**)&acc1,  g_acc1);
    cudaGetSymbolAddress((void**)&h2,    g_h2);
    cudaGetSymbolAddress((void**)&as,    g_as);
    cudaGetSymbolAddress((void**)&ad,    g_ad);
    cudaGetSymbolAddress((void**)&deg,   g_deg);
    cudaGetSymbolAddress((void**)&cur,   g_cur);
    cudaGetSymbolAddress((void**)&off,   g_off);
    cudaGetSymbolAddress((void**)&csrc,  g_csrc);
    cudaGetSymbolAddress((void**)&pool,  g_pool);
    cudaGetSymbolAddress((void**)&h1B,   g_h1B);
    cudaGetSymbolAddress((void**)&acc1B, g_acc1B);
    cudaGetSymbolAddress((void**)&h2B,   g_h2B);
    cudaGetSymbolAddress((void**)&asB,   g_asB);
    cudaGetSymbolAddress((void**)&adB,   g_adB);
    cudaGetSymbolAddress((void**)&degB,  g_degB);
    cudaGetSymbolAddress((void**)&curB,  g_curB);
    cudaGetSymbolAddress((void**)&offB,  g_offB);
    cudaGetSymbolAddress((void**)&csrcB, g_csrcB);
    cudaGetSymbolAddress((void**)&poolB, g_poolB);
    cudaGetSymbolAddress((void**)&cn,    g_cn);
    cudaGetSymbolAddress((void**)&c1,    g_c1);
    cudaGetSymbolAddress((void**)&c2,    g_c2);
    cudaGetSymbolAddress((void**)&xc,    g_xc);
    cudaGetSymbolAddress((void**)&f1,    g_f1);
    cudaGetSymbolAddress((void**)&f2,    g_f2);
    cudaGetSymbolAddress((void**)&f3,    g_f3);

    // fork: branch1 on the launch stream, branch2 + cell on side streams
    cudaStream_t s2, s3;
    cudaStreamCreateWithFlags(&s2, cudaStreamNonBlocking);
    cudaStreamCreateWithFlags(&s3, cudaStreamNonBlocking);
    cudaEvent_t e0, e2, e3;
    cudaEventCreateWithFlags(&e0, cudaEventDisableTiming);
    cudaEventCreateWithFlags(&e2, cudaEventDisableTiming);
    cudaEventCreateWithFlags(&e3, cudaEventDisableTiming);

    cudaEventRecord(e0, 0);
    cudaStreamWaitEvent(s2, e0, 0);
    cudaStreamWaitEvent(s3, e0, 0);

    // branch 1 -> xc[:, 0:128)
    run_branch(0,  x1, ei1, bt1, W1, aS1, aD1, b1, W2, aS2, aD2, b2, Wg, bg,
               h1, acc1, h2, as, ad, deg, cur, off, csrc, pool, xc);
    // branch 2 -> xc[:, 128:256)
    run_branch(s2, x2, ei2, bt2, W1, aS1, aD1, b1, W2, aS2, aD2, b2, Wg, bg,
               h1B, acc1B, h2B, asB, adB, degB, curB, offB, csrcB, poolB, xc + 128);
    // cell branch -> xc[:, 256:512)
    l2norm_k<<<N_GRAPH, 256, 0, s3>>>(cell, cn, FXT);
    gemm(s3, cn, Wr1, br1, c1, N_GRAPH, 2048, FXT, 2048, 1);
    gemm(s3, c1, Wr2, br2, c2, N_GRAPH, 512, 2048, 512, 1);
    gemm(s3, c2, Wr3, br3, xc + 256, N_GRAPH, 256, 512, 512, 1);

    // join
    cudaEventRecord(e2, s2);
    cudaEventRecord(e3, s3);
    cudaStreamWaitEvent(0, e2, 0);
    cudaStreamWaitEvent(0, e3, 0);

    // fuse head (launch stream)
    l2norm_k<<<N_GRAPH, 256>>>(xc, xc, 512);
    gemm(0, xc, Wf1, bf1, f1, N_GRAPH, 1024, 512, 1024, 1);
    gemm(0, f1, Wf2, bf2, f2, N_GRAPH, 512, 1024, 512, 1);
    gemm(0, f2, Wf3, bf3, f3, N_GRAPH, 128, 512, 128, 1);
    gemm(0, f3, Wo, bo, out, N_GRAPH, 2, 128, 2, 0);

    cudaEventDestroy(e0); cudaEventDestroy(e2); cudaEventDestroy(e3);
    cudaStreamDestroy(s2); cudaStreamDestroy(s3);
}

// round 14
// speedup vs baseline: 2.8570x; 1.1037x over previous
#include <cuda_runtime.h>
#include <math.h>
#include <stdint.h>

#define N_NODES 30000
#define N_EDGES 100000
#define EP      (N_EDGES + N_NODES)   // edges + self loops = 130000
#define N_GRAPH 1024
#define HEADS1  10
#define DCH     128
#define F1      1280                  // HEADS1 * DCH
#define FXD     78
#define FXT     954

// ---------------- scratch (device globals; no allocations allowed) ----------
// branch 1
__device__ float g_h1  [(size_t)N_NODES * F1];
__device__ float g_acc1[(size_t)N_NODES * F1];
__device__ float g_h2  [N_NODES * DCH];
__device__ float g_as  [N_NODES * HEADS1];
__device__ float g_ad  [N_NODES * HEADS1];
__device__ int   g_deg [N_NODES];
__device__ int   g_cur [N_NODES];
__device__ int   g_off [N_NODES + 1];
__device__ int   g_csrc[EP];
__device__ float g_pool[N_GRAPH * DCH];
// branch 2 (parallel execution -> fully separate scratch)
__device__ float g_h1B  [(size_t)N_NODES * F1];
__device__ float g_acc1B[(size_t)N_NODES * F1];
__device__ float g_h2B  [N_NODES * DCH];
__device__ float g_asB  [N_NODES * HEADS1];
__device__ float g_adB  [N_NODES * HEADS1];
__device__ int   g_degB [N_NODES];
__device__ int   g_curB [N_NODES];
__device__ int   g_offB [N_NODES + 1];
__device__ int   g_csrcB[EP];
__device__ float g_poolB[N_GRAPH * DCH];
// cell + head
__device__ float g_cn  [N_GRAPH * FXT];
__device__ float g_c1  [N_GRAPH * 2048];
__device__ float g_c2  [N_GRAPH * 512];
__device__ float g_xc  [N_GRAPH * 512];
__device__ float g_f1  [N_GRAPH * 1024];
__device__ float g_f2  [N_GRAPH * 512];
__device__ float g_f3  [N_GRAPH * 128];

// ---------------- helpers ----------------
__device__ __forceinline__ void atomicMaxF(float* a, float v) {
    if (v >= 0.f) atomicMax((int*)a, __float_as_int(v));
    else          atomicMin((unsigned int*)a, __float_as_uint(v));
}

__device__ __forceinline__ uint32_t f2tf32(float x) {
    uint32_t r;
    asm("cvt.rna.tf32.f32 %0, %1;" : "=r"(r) : "f"(x));
    return r;
}

__device__ __forceinline__ void mma_tf32(float c[4],
                                         uint32_t a0, uint32_t a1, uint32_t a2, uint32_t a3,
                                         uint32_t b0, uint32_t b1) {
    asm volatile("mma.sync.aligned.m16n8k8.row.col.f32.tf32.tf32.f32 "
                 "{%0,%1,%2,%3}, {%4,%5,%6,%7}, {%8,%9}, {%0,%1,%2,%3};"
                 : "+f"(c[0]), "+f"(c[1]), "+f"(c[2]), "+f"(c[3])
                 : "r"(a0), "r"(a1), "r"(a2), "r"(a3), "r"(b0), "r"(b1));
}

// ---------------- TF32 tensor-core GEMM (fragment-major SMEM, double buffer) -
#define TM 128
#define TN 128
#define TK 16
#define AF_WORDS 2048
#define BF_WORDS 2112

__global__ __launch_bounds__(256, 2)
void gemm_k(const float* __restrict__ A, const float* __restrict__ B,
            const float* __restrict__ bias, float* __restrict__ C,
            int M, int N, int K, int ldc, int act)
{
    __shared__ uint32_t AF[2][AF_WORDS];
    __shared__ uint32_t BF[2][BF_WORDS];

    int tid  = threadIdx.x;
    int wid  = tid >> 5, lane = tid & 31;
    int g    = lane >> 2, tg = lane & 3;
    int warpM = wid >> 2, warpN = wid & 3;
    int m0 = blockIdx.y * TM, n0 = blockIdx.x * TN;

    int ar     = tid >> 1;
    int mm     = ar & 15;
    int mtileS = ar >> 4;
    int kstepA = tid & 1;
    int br     = tid >> 5;
    int bcq    = tid & 31;
    int ntileS = bcq >> 1;
    int nnb    = (bcq & 1) * 4;

    float a_reg[8];
    float4 b_reg[2];

    auto loadA = [&](int k0) {
        int gm = m0 + ar;
        int kb = k0 + kstepA * 8;
        if (gm < M) {
            const float* ap = A + (size_t)gm * K + kb;
            if (((K & 3) == 0) && (kb + 7 < K)) {
                float4 v0 = *(const float4*)(ap);
                float4 v1 = *(const float4*)(ap + 4);
                a_reg[0] = v0.x; a_reg[1] = v0.y; a_reg[2] = v0.z; a_reg[3] = v0.w;
                a_reg[4] = v1.x; a_reg[5] = v1.y; a_reg[6] = v1.z; a_reg[7] = v1.w;
            } else {
                #pragma unroll
                for (int j = 0; j < 8; j++) {
                    int gk = kb + j;
                    a_reg[j] = (gk < K) ? ap[j] : 0.f;
                }
            }
        } else {
            #pragma unroll
            for (int j = 0; j < 8; j++) a_reg[j] = 0.f;
        }
    };
    auto loadB = [&](int k0) {
        #pragma unroll
        for (int it = 0; it < 2; it++) {
            int gk = k0 + br + it * 8;
            int gn = n0 + ntileS * 8 + nnb;
            float4 v = make_float4(0.f, 0.f, 0.f, 0.f);
            if (gk < K) {
                const float* bp = B + (size_t)gk * N + gn;
                if (gn + 3 < N) v = *(const float4*)bp;
                else {
                    if (gn     < N) v.x = bp[0];
                    if (gn + 1 < N) v.y = bp[1];
                    if (gn + 2 < N) v.z = bp[2];
                }
            }
            b_reg[it] = v;
        }
    };
    auto storeA = [&](int buf) {
        uint32_t* dst = AF[buf] + (kstepA * 8 + mtileS) * 128;
        #pragma unroll
        for (int j = 0; j < 8; j++) {
            int lane_f = (mm & 7) * 4 + (j & 3);
            int reg    = (mm >> 3) + 2 * (j >> 2);
            int chunk  = lane_f ^ ((lane_f >> 3) & 3);
            dst[chunk * 4 + reg] = f2tf32(a_reg[j]);
        }
    };
    auto storeB = [&](int buf) {
        int kb3 = br & 3, regb = br >> 2;
        #pragma unroll
        for (int pass = 0; pass < 2; pass++) {
            uint32_t* dst = BF[buf] + (pass * 16 + ntileS) * 66;
            float vv[4] = { b_reg[pass].x, b_reg[pass].y, b_reg[pass].z, b_reg[pass].w };
            #pragma unroll
            for (int jj = 0; jj < 4; jj++) {
                int lane_b = (nnb + jj) * 4 + kb3;
                dst[lane_b * 2 + regb] = f2tf32(vv[jj]);
            }
        }
    };

    float acc[4][4][4] = {};
    int clane = lane ^ ((lane >> 3) & 3);

    auto compute = [&](int buf) {
        #pragma unroll
        for (int ks = 0; ks < 2; ks++) {
            uint4 af4[4];
            uint2 bf2[4];
            #pragma unroll
            for (int i = 0; i < 4; i++)
                af4[i] = *(const uint4*)&AF[buf][((ks * 8 + warpM * 4 + i) * 32 + clane) * 4];
            #pragma unroll
            for (int u = 0; u < 4; u++)
                bf2[u] = *(const uint2*)&BF[buf][(ks * 16 + warpN * 4 + u) * 66 + lane * 2];
            #pragma unroll
            for (int i = 0; i < 4; i++)
                #pragma unroll
                for (int u = 0; u < 4; u++)
                    mma_tf32(acc[i][u], af4[i].x, af4[i].y, af4[i].z, af4[i].w,
                             bf2[u].x, bf2[u].y);
        }
    };

    int nk = (K + TK - 1) / TK;
    loadA(0); loadB(0);
    storeA(0); storeB(0);
    __syncthreads();

    for (int t = 0; t < nk; t++) {
        int cb = t & 1;
        if (t + 1 < nk) { loadA((t + 1) * TK); loadB((t + 1) * TK); }
        compute(cb);
        if (t + 1 < nk) { storeA(cb ^ 1); storeB(cb ^ 1); __syncthreads(); }
    }

    #pragma unroll
    for (int i = 0; i < 4; i++) {
        int mrow = m0 + warpM * 64 + i * 16 + g;
        #pragma unroll
        for (int u = 0; u < 4; u++) {
            int n = n0 + warpN * 32 + u * 8 + tg * 2;
            float b0 = 0.f, b1 = 0.f;
            if (bias) { if (n < N) b0 = bias[n]; if (n + 1 < N) b1 = bias[n + 1]; }
            #pragma unroll
            for (int half = 0; half < 2; half++) {
                int m = mrow + half * 8;
                if (m >= M) continue;
                float vx = acc[i][u][half * 2]     + b0;
                float vy = acc[i][u][half * 2 + 1] + b1;
                if (act == 1) { vx = fmaxf(vx, 0.f); vy = fmaxf(vy, 0.f); }
                if (n     < N) C[(size_t)m * ldc + n]     = vx;
                if (n + 1 < N) C[(size_t)m * ldc + n + 1] = vy;
            }
        }
    }
}

// ---------------- CSR build ----------------
__device__ __forceinline__ void edge_ends(int e, const int* __restrict__ ei,
                                          int& src, int& dst)
{
    if (e < N_EDGES) { src = ei[e]; dst = ei[N_EDGES + e]; }
    else             { src = dst = e - N_EDGES; }
}

__global__ void hist_k(const int* __restrict__ ei, int* __restrict__ deg) {
    int e = blockIdx.x * blockDim.x + threadIdx.x;
    if (e >= EP) return;
    int src, dst; edge_ends(e, ei, src, dst);
    (void)src;
    atomicAdd(&deg[dst], 1);
}

// single-block exclusive scan over N_NODES ints -> off[0..N_NODES]
__global__ void scan_k(const int* __restrict__ deg, int* __restrict__ off) {
    __shared__ int sm[1024];
    __shared__ int carry;
    if (threadIdx.x == 0) { carry = 0; off[0] = 0; }
    __syncthreads();
    for (int base = 0; base < N_NODES; base += 1024) {
        int i = base + threadIdx.x;
        int v = (i < N_NODES) ? deg[i] : 0;
        sm[threadIdx.x] = v;
        __syncthreads();
        #pragma unroll
        for (int s = 1; s < 1024; s <<= 1) {
            int t = (threadIdx.x >= s) ? sm[threadIdx.x - s] : 0;
            __syncthreads();
            sm[threadIdx.x] += t;
            __syncthreads();
        }
        if (i < N_NODES) off[i + 1] = carry + sm[threadIdx.x];
        __syncthreads();
        if (threadIdx.x == 0) carry += sm[1023];
        __syncthreads();
    }
}

__global__ void scatter_k(const int* __restrict__ ei, const int* __restrict__ off,
                          int* __restrict__ cur, int* __restrict__ csrc) {
    int e = blockIdx.x * blockDim.x + threadIdx.x;
    if (e >= EP) return;
    int src, dst; edge_ends(e, ei, src, dst);
    int pos = off[dst] + atomicAdd(&cur[dst], 1);
    csrc[pos] = src;
}

// ---------------- fused GAT softmax-aggregate ----------------
// HEAD-MAJOR warp mapping: a scheduling wave works within ONE head's h-slice
// (30000*128*4 = 15.3 MB), so the gathered h rows stay L2-resident and the
// 4.3x edge-multiplicity re-reads hit L2 instead of DRAM.
__global__ void gat_aggr_k(const int* __restrict__ off, const int* __restrict__ csrc,
                           const float* __restrict__ as, const float* __restrict__ ad,
                           const float* __restrict__ h, const float* __restrict__ bias,
                           float* __restrict__ outbuf, int heads)
{
    int w = (blockIdx.x * blockDim.x + threadIdx.x) >> 5;
    int lane = threadIdx.x & 31;
    if (w >= N_NODES * heads) return;
    int hd = w / N_NODES, n = w - hd * N_NODES;     // head-major
    int r0 = off[n], r1 = off[n + 1];
    float adn = ad[n * heads + hd];
    float4 acc = make_float4(0.f, 0.f, 0.f, 0.f);
    float den = 0.f;
    for (int e = r0; e < r1; e++) {
        int src = csrc[e];
        float v = as[src * heads + hd] + adn;
        v = v > 0.f ? v : 0.2f * v;
        float ex = __expf(v);
        den += ex;
        const float4 hv = *(const float4*)(h + ((size_t)src * heads + hd) * DCH + lane * 4);
        acc.x += ex * hv.x; acc.y += ex * hv.y; acc.z += ex * hv.z; acc.w += ex * hv.w;
    }
    float inv = 1.f / (den + 1e-16f);
    const float4 bb = *(const float4*)(bias + hd * DCH + lane * 4);
    float o0 = acc.x * inv + bb.x, o1 = acc.y * inv + bb.y;
    float o2 = acc.z * inv + bb.z, o3 = acc.w * inv + bb.w;
    o0 = o0 > 0.f ? o0 : __expf(o0) - 1.f;
    o1 = o1 > 0.f ? o1 : __expf(o1) - 1.f;
    o2 = o2 > 0.f ? o2 : __expf(o2) - 1.f;
    o3 = o3 > 0.f ? o3 : __expf(o3) - 1.f;
    *(float4*)(outbuf + ((size_t)n * heads + hd) * DCH + lane * 4) =
        make_float4(o0, o1, o2, o3);
}

__global__ void gat_aggr_pool_k(const int* __restrict__ off, const int* __restrict__ csrc,
                                const float* __restrict__ as, const float* __restrict__ ad,
                                const float* __restrict__ h, const float* __restrict__ bias,
                                const int* __restrict__ batch, float* __restrict__ pool)
{
    int n = (blockIdx.x * blockDim.x + threadIdx.x) >> 5;
    int lane = threadIdx.x & 31;
    if (n >= N_NODES) return;
    int r0 = off[n], r1 = off[n + 1];
    float adn = ad[n];
    float4 acc = make_float4(0.f, 0.f, 0.f, 0.f);
    float den = 0.f;
    for (int e = r0; e < r1; e++) {
        int src = csrc[e];
        float v = as[src] + adn;
        v = v > 0.f ? v : 0.2f * v;
        float ex = __expf(v);
        den += ex;
        const float4 hv = *(const float4*)(h + (size_t)src * DCH + lane * 4);
        acc.x += ex * hv.x; acc.y += ex * hv.y; acc.z += ex * hv.z; acc.w += ex * hv.w;
    }
    float inv = 1.f / (den + 1e-16f);
    const float4 bb = *(const float4*)(bias + lane * 4);
    float o[4];
    o[0] = acc.x * inv + bb.x; o[1] = acc.y * inv + bb.y;
    o[2] = acc.z * inv + bb.z; o[3] = acc.w * inv + bb.w;
    float* pp = pool + (size_t)batch[n] * DCH + lane * 4;
    #pragma unroll
    for (int j = 0; j < 4; j++) {
        float v = o[j] > 0.f ? o[j] : __expf(o[j]) - 1.f;
        atomicMaxF(pp + j, v);
    }
}

// ---------------- elementwise ----------------
__global__ void fill4_k(float4* __restrict__ p, float v, int n4) {
    int t = blockIdx.x * blockDim.x + threadIdx.x;
    if (t < n4) p[t] = make_float4(v, v, v, v);
}

__global__ void alpha_k(const float* __restrict__ h,
                        const float* __restrict__ a_s, const float* __restrict__ a_d,
                        float* __restrict__ os, float* __restrict__ od,
                        int n, int heads)
{
    int t = blockIdx.x * blockDim.x + threadIdx.x;
    if (t >= n * heads) return;
    int hd = t % heads;
    const float* hp = h + (size_t)t * DCH;
    const float* sp = a_s + hd * DCH;
    const float* dp = a_d + hd * DCH;
    float s1 = 0.f, s2 = 0.f;
    #pragma unroll 8
    for (int c = 0; c < DCH; c += 4) {
        float4 hv = *(const float4*)(hp + c);
        float4 sv = *(const float4*)(sp + c);
        float4 dv = *(const float4*)(dp + c);
        s1 += hv.x * sv.x + hv.y * sv.y + hv.z * sv.z + hv.w * sv.w;
        s2 += hv.x * dv.x + hv.y * dv.y + hv.z * dv.z + hv.w * dv.w;
    }
    os[t] = s1;
    od[t] = s2;
}

__global__ void l2norm_k(const float* __restrict__ in, float* __restrict__ out, int cols)
{
    __shared__ float red[256];
    int row = blockIdx.x;
    const float* ip = in + (size_t)row * cols;
    float s = 0.f;
    for (int c = threadIdx.x; c < cols; c += 256) { float v = ip[c]; s += v * v; }
    red[threadIdx.x] = s;
    __syncthreads();
    for (int off = 128; off > 0; off >>= 1) {
        if (threadIdx.x < off) red[threadIdx.x] += red[threadIdx.x + off];
        __syncthreads();
    }
    float sc = 1.f / fmaxf(sqrtf(red[0]), 1e-12f);
    float* op = out + (size_t)row * cols;
    for (int c = threadIdx.x; c < cols; c += 256) op[c] = ip[c] * sc;
}

// ---------------- host orchestration ----------------
static void gemm(cudaStream_t st, const float* A, const float* B, const float* bias,
                 float* C, int M, int N, int K, int ldc, int act)
{
    dim3 grid((N + TN - 1) / TN, (M + TM - 1) / TM);
    gemm_k<<<grid, 256, 0, st>>>(A, B, bias, C, M, N, K, ldc, act);
}

static void run_branch(cudaStream_t st,
                       const float* x, const int* ei, const int* batch,
                       const float* W1, const float* a_s1, const float* a_d1, const float* b1,
                       const float* W2, const float* a_s2, const float* a_d2, const float* b2,
                       const float* Wg, const float* bg,
                       float* h1, float* acc1, float* h2,
                       float* as, float* ad,
                       int* deg, int* cur, int* off, int* csrc,
                       float* pool, float* vout)
{
    const int T = 256;
    // --- CSR build (shared by both layers) ---
    cudaMemsetAsync(deg, 0, N_NODES * 4, st);
    cudaMemsetAsync(cur, 0, N_NODES * 4, st);
    hist_k<<<(EP + T - 1) / T, T, 0, st>>>(ei, deg);
    scan_k<<<1, 1024, 0, st>>>(deg, off);
    scatter_k<<<(EP + T - 1) / T, T, 0, st>>>(ei, off, cur, csrc);

    // --- GATConv1 (H=10, D=128) ---
    gemm(st, x, W1, nullptr, h1, N_NODES, F1, FXD, F1, 0);
    alpha_k<<<(N_NODES * HEADS1 + T - 1) / T, T, 0, st>>>(h1, a_s1, a_d1, as, ad,
                                                          N_NODES, HEADS1);
    gat_aggr_k<<<((size_t)N_NODES * HEADS1 * 32 + T - 1) / T, T, 0, st>>>(
        off, csrc, as, ad, h1, b1, acc1, HEADS1);

    // --- GATConv2 (H=1, D=128) + fused max pool ---
    gemm(st, acc1, W2, nullptr, h2, N_NODES, DCH, F1, DCH, 0);
    alpha_k<<<(N_NODES + T - 1) / T, T, 0, st>>>(h2, a_s2, a_d2, as, ad, N_NODES, 1);
    fill4_k<<<(N_GRAPH * DCH / 4 + T - 1) / T, T, 0, st>>>((float4*)pool, -INFINITY,
                                                           N_GRAPH * DCH / 4);
    gat_aggr_pool_k<<<((size_t)N_NODES * 32 + T - 1) / T, T, 0, st>>>(
        off, csrc, as, ad, h2, b2, batch, pool);
    gemm(st, pool, Wg, bg, vout, N_GRAPH, DCH, DCH, 512, 1);
}

extern "C" void kernel_launch(void* const* d_in, const int* in_sizes, int n_in,
                              void* d_out, int out_size)
{
    const float* x1   = (const float*)d_in[0];
    const int*   ei1  = (const int*)  d_in[1];
    const int*   bt1  = (const int*)  d_in[2];
    const float* x2   = (const float*)d_in[3];
    const int*   ei2  = (const int*)  d_in[4];
    const int*   bt2  = (const int*)  d_in[5];
    const float* cell = (const float*)d_in[6];
    const float* W1   = (const float*)d_in[7];
    const float* aS1  = (const float*)d_in[8];
    const float* aD1  = (const float*)d_in[9];
    const float* b1   = (const float*)d_in[10];
    const float* W2   = (const float*)d_in[11];
    const float* aS2  = (const float*)d_in[12];
    const float* aD2  = (const float*)d_in[13];
    const float* b2   = (const float*)d_in[14];
    const float* Wg   = (const float*)d_in[15];
    const float* bg   = (const float*)d_in[16];
    const float* Wr1  = (const float*)d_in[17];
    const float* br1  = (const float*)d_in[18];
    const float* Wr2  = (const float*)d_in[19];
    const float* br2  = (const float*)d_in[20];
    const float* Wr3  = (const float*)d_in[21];
    const float* br3  = (const float*)d_in[22];
    const float* Wf1  = (const float*)d_in[23];
    const float* bf1  = (const float*)d_in[24];
    const float* Wf2  = (const float*)d_in[25];
    const float* bf2  = (const float*)d_in[26];
    const float* Wf3  = (const float*)d_in[27];
    const float* bf3  = (const float*)d_in[28];
    const float* Wo   = (const float*)d_in[29];
    const float* bo   = (const float*)d_in[30];
    float* out = (float*)d_out;

    float *h1, *acc1, *h2, *as, *ad, *pool;
    float *h1B, *acc1B, *h2B, *asB, *adB, *poolB;
    float *cn, *c1, *c2, *xc, *f1, *f2, *f3;
    int *deg, *cur, *off, *csrc, *degB, *curB, *offB, *csrcB;
    cudaGetSymbolAddress((void**)&h1,    g_h1);
    cudaGetSymbolAddress((void**)&acc1,  g_acc1);
    cudaGetSymbolAddress((void**)&h2,    g_h2);
    cudaGetSymbolAddress((void**)&as,    g_as);
    cudaGetSymbolAddress((void**)&ad,    g_ad);
    cudaGetSymbolAddress((void**)&deg,   g_deg);
    cudaGetSymbolAddress((void**)&cur,   g_cur);
    cudaGetSymbolAddress((void**)&off,   g_off);
    cudaGetSymbolAddress((void**)&csrc,  g_csrc);
    cudaGetSymbolAddress((void**)&pool,  g_pool);
    cudaGetSymbolAddress((void**)&h1B,   g_h1B);
    cudaGetSymbolAddress((void**)&acc1B, g_acc1B);
    cudaGetSymbolAddress((void**)&h2B,   g_h2B);
    cudaGetSymbolAddress((void**)&asB,   g_asB);
    cudaGetSymbolAddress((void**)&adB,   g_adB);
    cudaGetSymbolAddress((void**)&degB,  g_degB);
    cudaGetSymbolAddress((void**)&curB,  g_curB);
    cudaGetSymbolAddress((void**)&offB,  g_offB);
    cudaGetSymbolAddress((void**)&csrcB, g_csrcB);
    cudaGetSymbolAddress((void**)&poolB, g_poolB);
    cudaGetSymbolAddress((void**)&cn,    g_cn);
    cudaGetSymbolAddress((void**)&c1,    g_c1);
    cudaGetSymbolAddress((void**)&c2,    g_c2);
    cudaGetSymbolAddress((void**)&xc,    g_xc);
    cudaGetSymbolAddress((void**)&f1,    g_f1);
    cudaGetSymbolAddress((void**)&f2,    g_f2);
    cudaGetSymbolAddress((void**)&f3,    g_f3);

    // fork: branch1 on the launch stream, branch2 + cell on side streams
    cudaStream_t s2, s3;
    cudaStreamCreateWithFlags(&s2, cudaStreamNonBlocking);
    cudaStreamCreateWithFlags(&s3, cudaStreamNonBlocking);
    cudaEvent_t e0, e2, e3;
    cudaEventCreateWithFlags(&e0, cudaEventDisableTiming);
    cudaEventCreateWithFlags(&e2, cudaEventDisableTiming);
    cudaEventCreateWithFlags(&e3, cudaEventDisableTiming);

    cudaEventRecord(e0, 0);
    cudaStreamWaitEvent(s2, e0, 0);
    cudaStreamWaitEvent(s3, e0, 0);

    // branch 1 -> xc[:, 0:128)
    run_branch(0,  x1, ei1, bt1, W1, aS1, aD1, b1, W2, aS2, aD2, b2, Wg, bg,
               h1, acc1, h2, as, ad, deg, cur, off, csrc, pool, xc);
    // branch 2 -> xc[:, 128:256)
    run_branch(s2, x2, ei2, bt2, W1, aS1, aD1, b1, W2, aS2, aD2, b2, Wg, bg,
               h1B, acc1B, h2B, asB, adB, degB, curB, offB, csrcB, poolB, xc + 128);
    // cell branch -> xc[:, 256:512)
    l2norm_k<<<N_GRAPH, 256, 0, s3>>>(cell, cn, FXT);
    gemm(s3, cn, Wr1, br1, c1, N_GRAPH, 2048, FXT, 2048, 1);
    gemm(s3, c1, Wr2, br2, c2, N_GRAPH, 512, 2048, 512, 1);
    gemm(s3, c2, Wr3, br3, xc + 256, N_GRAPH, 256, 512, 512, 1);

    // join
    cudaEventRecord(e2, s2);
    cudaEventRecord(e3, s3);
    cudaStreamWaitEvent(0, e2, 0);
    cudaStreamWaitEvent(0, e3, 0);

    // fuse head (launch stream)
    l2norm_k<<<N_GRAPH, 256>>>(xc, xc, 512);
    gemm(0, xc, Wf1, bf1, f1, N_GRAPH, 1024, 512, 1024, 1);
    gemm(0, f1, Wf2, bf2, f2, N_GRAPH, 512, 1024, 512, 1);
    gemm(0, f2, Wf3, bf3, f3, N_GRAPH, 128, 512, 128, 1);
    gemm(0, f3, Wo, bo, out, N_GRAPH, 2, 128, 2, 0);

    cudaEventDestroy(e0); cudaEventDestroy(e2); cudaEventDestroy(e3);
    cudaStreamDestroy(s2); cudaStreamDestroy(s3);
}

// round 15
// speedup vs baseline: 3.3860x; 1.1852x over previous
#include <cuda_runtime.h>
#include <math.h>
#include <stdint.h>

#define N_NODES 30000
#define N_EDGES 100000
#define EP      (N_EDGES + N_NODES)   // edges + self loops = 130000
#define N_GRAPH 1024
#define HEADS1  10
#define DCH     128
#define F1      1280                  // HEADS1 * DCH
#define FXD     78
#define FXT     954

// ---------------- scratch (device globals; no allocations allowed) ----------
// branch 1
__device__ float g_h1  [(size_t)N_NODES * F1];
__device__ float g_acc1[(size_t)N_NODES * F1];
__device__ float g_h2  [N_NODES * DCH];
__device__ float g_as  [N_NODES * HEADS1];
__device__ float g_ad  [N_NODES * HEADS1];
__device__ int   g_deg [N_NODES];
__device__ int   g_cur [N_NODES];
__device__ int   g_off [N_NODES + 1];
__device__ int   g_csrc[EP];
__device__ float g_pool[N_GRAPH * DCH];
// branch 2 (parallel execution -> fully separate scratch)
__device__ float g_h1B  [(size_t)N_NODES * F1];
__device__ float g_acc1B[(size_t)N_NODES * F1];
__device__ float g_h2B  [N_NODES * DCH];
__device__ float g_asB  [N_NODES * HEADS1];
__device__ float g_adB  [N_NODES * HEADS1];
__device__ int   g_degB [N_NODES];
__device__ int   g_curB [N_NODES];
__device__ int   g_offB [N_NODES + 1];
__device__ int   g_csrcB[EP];
__device__ float g_poolB[N_GRAPH * DCH];
// cell + head
__device__ float g_cn  [N_GRAPH * FXT];
__device__ float g_c1  [N_GRAPH * 2048];
__device__ float g_c2  [N_GRAPH * 512];
__device__ float g_xc  [N_GRAPH * 512];
__device__ float g_f1  [N_GRAPH * 1024];
__device__ float g_f2  [N_GRAPH * 512];
__device__ float g_f3  [N_GRAPH * 128];
// projected attention vectors (layer 1)
__device__ float g_Was [FXD * HEADS1];
__device__ float g_Wad [FXD * HEADS1];
// pre-shuffled fragment-major tf32 weights (one pool, static offsets)
#define SH_W1   0
#define SH_W2   (SH_W1  + 102400)   // W1:  kt=5,  nt=10
#define SH_WG   (SH_W2  + 163840)   // W2:  kt=80, nt=1
#define SH_WR1  (SH_WG  + 16384)    // Wg:  kt=8,  nt=1
#define SH_WR2  (SH_WR1 + 1966080)  // Wr1: kt=60, nt=16
#define SH_WR3  (SH_WR2 + 1048576)  // Wr2: kt=128,nt=4
#define SH_WF1  (SH_WR3 + 131072)   // Wr3: kt=32, nt=2
#define SH_WF2  (SH_WF1 + 524288)   // Wf1: kt=32, nt=8
#define SH_WF3  (SH_WF2 + 524288)   // Wf2: kt=64, nt=4
#define SH_WO   (SH_WF3 + 65536)    // Wf3: kt=32, nt=1
#define SH_END  (SH_WO  + 16384)    // Wo:  kt=8,  nt=1
__device__ uint32_t g_wsh[SH_END];

// ---------------- helpers ----------------
__device__ __forceinline__ void atomicMaxF(float* a, float v) {
    if (v >= 0.f) atomicMax((int*)a, __float_as_int(v));
    else          atomicMin((unsigned int*)a, __float_as_uint(v));
}

__device__ __forceinline__ uint32_t f2tf32(float x) {
    uint32_t r;
    asm("cvt.rna.tf32.f32 %0, %1;" : "=r"(r) : "f"(x));
    return r;
}

__device__ __forceinline__ void mma_tf32(float c[4],
                                         uint32_t a0, uint32_t a1, uint32_t a2, uint32_t a3,
                                         uint32_t b0, uint32_t b1) {
    asm volatile("mma.sync.aligned.m16n8k8.row.col.f32.tf32.tf32.f32 "
                 "{%0,%1,%2,%3}, {%4,%5,%6,%7}, {%8,%9}, {%0,%1,%2,%3};"
                 : "+f"(c[0]), "+f"(c[1]), "+f"(c[2]), "+f"(c[3])
                 : "r"(a0), "r"(a1), "r"(a2), "r"(a3), "r"(b0), "r"(b1));
}

// ---------------- weight pre-shuffle: row-major f32 -> fragment-major tf32 ---
// word index inside a (16k x 128n) tile: (kstep*16 + ntile)*64 + lane*2 + reg
// maps to B[kt*16 + kstep*8 + (lane&3) + reg*4][nt*128 + ntile*8 + (lane>>2)]
__global__ void shufB_k(const float* __restrict__ B, uint32_t* __restrict__ out,
                        int K, int N, int total)
{
    int idx = blockIdx.x * blockDim.x + threadIdx.x;
    if (idx >= total) return;
    int ntc = (N + 127) >> 7;
    int tile = idx >> 11, w = idx & 2047;
    int kt = tile / ntc, nt = tile - kt * ntc;
    int row = w >> 6;                 // kstep*16 + ntile
    int kstep = row >> 4, ntile = row & 15;
    int lane = (w >> 1) & 31, reg = w & 1;
    int k = kt * 16 + kstep * 8 + (lane & 3) + reg * 4;
    int n = nt * 128 + ntile * 8 + (lane >> 2);
    float v = (k < K && n < N) ? B[(size_t)k * N + n] : 0.f;
    out[idx] = f2tf32(v);
}

// ---------------- TF32 tensor-core GEMM ---------------------------------------
// A: row-major f32 (staged fragment-major with tf32 cvt).
// B: PRE-SHUFFLED fragment-major tf32 in global -> cp.async 16B direct to SMEM.
#define TM 128
#define TN 128
#define TK 16
#define AF_WORDS 2048
#define BF_WORDS 2048

__global__ __launch_bounds__(256, 2)
void gemm_k(const float* __restrict__ A, const uint32_t* __restrict__ Bsh,
            const float* __restrict__ bias, float* __restrict__ C,
            int M, int N, int K, int ldc, int act)
{
    __shared__ uint32_t AF[2][AF_WORDS];
    __shared__ uint32_t BF[2][BF_WORDS];

    int tid  = threadIdx.x;
    int wid  = tid >> 5, lane = tid & 31;
    int g    = lane >> 2, tg = lane & 3;
    int warpM = wid >> 2, warpN = wid & 3;
    int m0 = blockIdx.y * TM, n0 = blockIdx.x * TN;

    int ar     = tid >> 1;
    int mm     = ar & 15;
    int mtileS = ar >> 4;
    int kstepA = tid & 1;

    float a_reg[8];

    auto loadA = [&](int k0) {
        int gm = m0 + ar;
        int kb = k0 + kstepA * 8;
        if (gm < M) {
            const float* ap = A + (size_t)gm * K + kb;
            if (((K & 3) == 0) && (kb + 7 < K)) {
                float4 v0 = *(const float4*)(ap);
                float4 v1 = *(const float4*)(ap + 4);
                a_reg[0] = v0.x; a_reg[1] = v0.y; a_reg[2] = v0.z; a_reg[3] = v0.w;
                a_reg[4] = v1.x; a_reg[5] = v1.y; a_reg[6] = v1.z; a_reg[7] = v1.w;
            } else {
                #pragma unroll
                for (int j = 0; j < 8; j++) {
                    int gk = kb + j;
                    a_reg[j] = (gk < K) ? ap[j] : 0.f;
                }
            }
        } else {
            #pragma unroll
            for (int j = 0; j < 8; j++) a_reg[j] = 0.f;
        }
    };
    auto storeA = [&](int buf) {
        uint32_t* dst = AF[buf] + (kstepA * 8 + mtileS) * 128;
        #pragma unroll
        for (int j = 0; j < 8; j++) {
            int lane_f = (mm & 7) * 4 + (j & 3);
            int reg    = (mm >> 3) + 2 * (j >> 2);
            int chunk  = lane_f ^ ((lane_f >> 3) & 3);
            dst[chunk * 4 + reg] = f2tf32(a_reg[j]);
        }
    };
    auto cpB = [&](int t, int buf) {
        size_t base = ((size_t)t * gridDim.x + blockIdx.x) * 2048;
        const uint32_t* src = Bsh + base;
        #pragma unroll
        for (int it = 0; it < 2; it++) {
            int w = (tid + it * 256) * 4;
            uint32_t sa = (uint32_t)__cvta_generic_to_shared(&BF[buf][w]);
            asm volatile("cp.async.cg.shared.global [%0], [%1], 16;"
                         :: "r"(sa), "l"(src + w) : "memory");
        }
    };

    float acc[4][4][4] = {};
    int clane = lane ^ ((lane >> 3) & 3);

    auto compute = [&](int buf) {
        #pragma unroll
        for (int ks = 0; ks < 2; ks++) {
            uint4 af4[4];
            uint2 bf2[4];
            #pragma unroll
            for (int i = 0; i < 4; i++)
                af4[i] = *(const uint4*)&AF[buf][((ks * 8 + warpM * 4 + i) * 32 + clane) * 4];
            #pragma unroll
            for (int u = 0; u < 4; u++)
                bf2[u] = *(const uint2*)&BF[buf][(ks * 16 + warpN * 4 + u) * 64 + lane * 2];
            #pragma unroll
            for (int i = 0; i < 4; i++)
                #pragma unroll
                for (int u = 0; u < 4; u++)
                    mma_tf32(acc[i][u], af4[i].x, af4[i].y, af4[i].z, af4[i].w,
                             bf2[u].x, bf2[u].y);
        }
    };

    int nk = (K + TK - 1) / TK;
    loadA(0); storeA(0);
    cpB(0, 0);
    asm volatile("cp.async.commit_group;" ::: "memory");
    asm volatile("cp.async.wait_group 0;" ::: "memory");
    __syncthreads();

    for (int t = 0; t < nk; t++) {
        int cb = t & 1;
        if (t + 1 < nk) {
            loadA((t + 1) * TK);
            cpB(t + 1, cb ^ 1);
            asm volatile("cp.async.commit_group;" ::: "memory");
        }
        compute(cb);
        if (t + 1 < nk) {
            storeA(cb ^ 1);
            asm volatile("cp.async.wait_group 0;" ::: "memory");
            __syncthreads();
        }
    }

    #pragma unroll
    for (int i = 0; i < 4; i++) {
        int mrow = m0 + warpM * 64 + i * 16 + g;
        #pragma unroll
        for (int u = 0; u < 4; u++) {
            int n = n0 + warpN * 32 + u * 8 + tg * 2;
            float b0 = 0.f, b1 = 0.f;
            if (bias) { if (n < N) b0 = bias[n]; if (n + 1 < N) b1 = bias[n + 1]; }
            #pragma unroll
            for (int half = 0; half < 2; half++) {
                int m = mrow + half * 8;
                if (m >= M) continue;
                float vx = acc[i][u][half * 2]     + b0;
                float vy = acc[i][u][half * 2 + 1] + b1;
                if (act == 1) { vx = fmaxf(vx, 0.f); vy = fmaxf(vy, 0.f); }
                if (n     < N) C[(size_t)m * ldc + n]     = vx;
                if (n + 1 < N) C[(size_t)m * ldc + n + 1] = vy;
            }
        }
    }
}

// ---------------- layer-1 attention projection ----------------
// Was[k,hd] = sum_c W1[k, hd*128+c] * aS[hd,c]  (and same for Wad)
__global__ void proj_att_k(const float* __restrict__ W1,
                           const float* __restrict__ aS, const float* __restrict__ aD,
                           float* __restrict__ Was, float* __restrict__ Wad)
{
    int t = blockIdx.x * blockDim.x + threadIdx.x;
    if (t >= FXD * HEADS1) return;
    int k = t / HEADS1, hd = t - (t / HEADS1) * HEADS1;
    const float* wr = W1 + (size_t)k * F1 + hd * DCH;
    const float* sr = aS + hd * DCH;
    const float* dr = aD + hd * DCH;
    float s1 = 0.f, s2 = 0.f;
    #pragma unroll 4
    for (int c = 0; c < DCH; c++) { float w = wr[c]; s1 += w * sr[c]; s2 += w * dr[c]; }
    Was[t] = s1;
    Wad[t] = s2;
}

// as[n,hd] = x[n,:] @ Was[:,hd]   (exact fp32; replaces alpha pass over h1)
__global__ void alpha_x_k(const float* __restrict__ x,
                          const float* __restrict__ Was, const float* __restrict__ Wad,
                          float* __restrict__ as, float* __restrict__ ad)
{
    int t = blockIdx.x * blockDim.x + threadIdx.x;
    if (t >= N_NODES * HEADS1) return;
    int n = t / HEADS1, hd = t - (t / HEADS1) * HEADS1;
    const float* xr = x + (size_t)n * FXD;
    float s1 = 0.f, s2 = 0.f;
    #pragma unroll 6
    for (int k = 0; k < FXD; k++) {
        float xv = xr[k];
        s1 += xv * Was[k * HEADS1 + hd];
        s2 += xv * Wad[k * HEADS1 + hd];
    }
    as[t] = s1;
    ad[t] = s2;
}

// ---------------- CSR build ----------------
__device__ __forceinline__ void edge_ends(int e, const int* __restrict__ ei,
                                          int& src, int& dst)
{
    if (e < N_EDGES) { src = ei[e]; dst = ei[N_EDGES + e]; }
    else             { src = dst = e - N_EDGES; }
}

__global__ void hist_k(const int* __restrict__ ei, int* __restrict__ deg) {
    int e = blockIdx.x * blockDim.x + threadIdx.x;
    if (e >= EP) return;
    int src, dst; edge_ends(e, ei, src, dst);
    (void)src;
    atomicAdd(&deg[dst], 1);
}

__global__ void scan_k(const int* __restrict__ deg, int* __restrict__ off) {
    __shared__ int sm[1024];
    __shared__ int carry;
    if (threadIdx.x == 0) { carry = 0; off[0] = 0; }
    __syncthreads();
    for (int base = 0; base < N_NODES; base += 1024) {
        int i = base + threadIdx.x;
        int v = (i < N_NODES) ? deg[i] : 0;
        sm[threadIdx.x] = v;
        __syncthreads();
        #pragma unroll
        for (int s = 1; s < 1024; s <<= 1) {
            int t = (threadIdx.x >= s) ? sm[threadIdx.x - s] : 0;
            __syncthreads();
            sm[threadIdx.x] += t;
            __syncthreads();
        }
        if (i < N_NODES) off[i + 1] = carry + sm[threadIdx.x];
        __syncthreads();
        if (threadIdx.x == 0) carry += sm[1023];
        __syncthreads();
    }
}

__global__ void scatter_k(const int* __restrict__ ei, const int* __restrict__ off,
                          int* __restrict__ cur, int* __restrict__ csrc) {
    int e = blockIdx.x * blockDim.x + threadIdx.x;
    if (e >= EP) return;
    int src, dst; edge_ends(e, ei, src, dst);
    int pos = off[dst] + atomicAdd(&cur[dst], 1);
    csrc[pos] = src;
}

// ---------------- fused GAT softmax-aggregate (head-major) ----------------
__global__ void gat_aggr_k(const int* __restrict__ off, const int* __restrict__ csrc,
                           const float* __restrict__ as, const float* __restrict__ ad,
                           const float* __restrict__ h, const float* __restrict__ bias,
                           float* __restrict__ outbuf, int heads)
{
    int w = (blockIdx.x * blockDim.x + threadIdx.x) >> 5;
    int lane = threadIdx.x & 31;
    if (w >= N_NODES * heads) return;
    int hd = w / N_NODES, n = w - hd * N_NODES;     // head-major
    int r0 = off[n], r1 = off[n + 1];
    float adn = ad[n * heads + hd];
    float4 acc = make_float4(0.f, 0.f, 0.f, 0.f);
    float den = 0.f;
    for (int e = r0; e < r1; e++) {
        int src = csrc[e];
        float v = as[src * heads + hd] + adn;
        v = v > 0.f ? v : 0.2f * v;
        float ex = __expf(v);
        den += ex;
        const float4 hv = *(const float4*)(h + ((size_t)src * heads + hd) * DCH + lane * 4);
        acc.x += ex * hv.x; acc.y += ex * hv.y; acc.z += ex * hv.z; acc.w += ex * hv.w;
    }
    float inv = 1.f / (den + 1e-16f);
    const float4 bb = *(const float4*)(bias + hd * DCH + lane * 4);
    float o0 = acc.x * inv + bb.x, o1 = acc.y * inv + bb.y;
    float o2 = acc.z * inv + bb.z, o3 = acc.w * inv + bb.w;
    o0 = o0 > 0.f ? o0 : __expf(o0) - 1.f;
    o1 = o1 > 0.f ? o1 : __expf(o1) - 1.f;
    o2 = o2 > 0.f ? o2 : __expf(o2) - 1.f;
    o3 = o3 > 0.f ? o3 : __expf(o3) - 1.f;
    *(float4*)(outbuf + ((size_t)n * heads + hd) * DCH + lane * 4) =
        make_float4(o0, o1, o2, o3);
}

__global__ void gat_aggr_pool_k(const int* __restrict__ off, const int* __restrict__ csrc,
                                const float* __restrict__ as, const float* __restrict__ ad,
                                const float* __restrict__ h, const float* __restrict__ bias,
                                const int* __restrict__ batch, float* __restrict__ pool)
{
    int n = (blockIdx.x * blockDim.x + threadIdx.x) >> 5;
    int lane = threadIdx.x & 31;
    if (n >= N_NODES) return;
    int r0 = off[n], r1 = off[n + 1];
    float adn = ad[n];
    float4 acc = make_float4(0.f, 0.f, 0.f, 0.f);
    float den = 0.f;
    for (int e = r0; e < r1; e++) {
        int src = csrc[e];
        float v = as[src] + adn;
        v = v > 0.f ? v : 0.2f * v;
        float ex = __expf(v);
        den += ex;
        const float4 hv = *(const float4*)(h + (size_t)src * DCH + lane * 4);
        acc.x += ex * hv.x; acc.y += ex * hv.y; acc.z += ex * hv.z; acc.w += ex * hv.w;
    }
    float inv = 1.f / (den + 1e-16f);
    const float4 bb = *(const float4*)(bias + lane * 4);
    float o[4];
    o[0] = acc.x * inv + bb.x; o[1] = acc.y * inv + bb.y;
    o[2] = acc.z * inv + bb.z; o[3] = acc.w * inv + bb.w;
    float* pp = pool + (size_t)batch[n] * DCH + lane * 4;
    #pragma unroll
    for (int j = 0; j < 4; j++) {
        float v = o[j] > 0.f ? o[j] : __expf(o[j]) - 1.f;
        atomicMaxF(pp + j, v);
    }
}

// ---------------- elementwise ----------------
__global__ void fill4_k(float4* __restrict__ p, float v, int n4) {
    int t = blockIdx.x * blockDim.x + threadIdx.x;
    if (t < n4) p[t] = make_float4(v, v, v, v);
}

__global__ void alpha_k(const float* __restrict__ h,
                        const float* __restrict__ a_s, const float* __restrict__ a_d,
                        float* __restrict__ os, float* __restrict__ od,
                        int n, int heads)
{
    int t = blockIdx.x * blockDim.x + threadIdx.x;
    if (t >= n * heads) return;
    int hd = t % heads;
    const float* hp = h + (size_t)t * DCH;
    const float* sp = a_s + hd * DCH;
    const float* dp = a_d + hd * DCH;
    float s1 = 0.f, s2 = 0.f;
    #pragma unroll 8
    for (int c = 0; c < DCH; c += 4) {
        float4 hv = *(const float4*)(hp + c);
        float4 sv = *(const float4*)(sp + c);
        float4 dv = *(const float4*)(dp + c);
        s1 += hv.x * sv.x + hv.y * sv.y + hv.z * sv.z + hv.w * sv.w;
        s2 += hv.x * dv.x + hv.y * dv.y + hv.z * dv.z + hv.w * dv.w;
    }
    os[t] = s1;
    od[t] = s2;
}

__global__ void l2norm_k(const float* __restrict__ in, float* __restrict__ out, int cols)
{
    __shared__ float red[256];
    int row = blockIdx.x;
    const float* ip = in + (size_t)row * cols;
    float s = 0.f;
    for (int c = threadIdx.x; c < cols; c += 256) { float v = ip[c]; s += v * v; }
    red[threadIdx.x] = s;
    __syncthreads();
    for (int off = 128; off > 0; off >>= 1) {
        if (threadIdx.x < off) red[threadIdx.x] += red[threadIdx.x + off];
        __syncthreads();
    }
    float sc = 1.f / fmaxf(sqrtf(red[0]), 1e-12f);
    float* op = out + (size_t)row * cols;
    for (int c = threadIdx.x; c < cols; c += 256) op[c] = ip[c] * sc;
}

// ---------------- host orchestration ----------------
static void shuf(cudaStream_t st, const float* B, uint32_t* out, int K, int N)
{
    int total = ((K + 15) / 16) * ((N + 127) / 128) * 2048;
    shufB_k<<<(total + 255) / 256, 256, 0, st>>>(B, out, K, N, total);
}

static void gemm(cudaStream_t st, const float* A, const uint32_t* Bsh, const float* bias,
                 float* C, int M, int N, int K, int ldc, int act)
{
    dim3 grid((N + TN - 1) / TN, (M + TM - 1) / TM);
    gemm_k<<<grid, 256, 0, st>>>(A, Bsh, bias, C, M, N, K, ldc, act);
}

static void run_branch(cudaStream_t st,
                       const float* x, const int* ei, const int* batch,
                       const uint32_t* W1sh, const float* Was, const float* Wad,
                       const float* b1,
                       const uint32_t* W2sh, const float* a_s2, const float* a_d2,
                       const float* b2,
                       const uint32_t* Wgsh, const float* bg,
                       float* h1, float* acc1, float* h2,
                       float* as, float* ad,
                       int* deg, int* cur, int* off, int* csrc,
                       float* pool, float* vout)
{
    const int T = 256;
    // --- CSR build (shared by both layers) ---
    cudaMemsetAsync(deg, 0, N_NODES * 4, st);
    cudaMemsetAsync(cur, 0, N_NODES * 4, st);
    hist_k<<<(EP + T - 1) / T, T, 0, st>>>(ei, deg);
    scan_k<<<1, 1024, 0, st>>>(deg, off);
    scatter_k<<<(EP + T - 1) / T, T, 0, st>>>(ei, off, cur, csrc);

    // --- GATConv1 (H=10, D=128) ---
    alpha_x_k<<<(N_NODES * HEADS1 + T - 1) / T, T, 0, st>>>(x, Was, Wad, as, ad);
    gemm(st, x, W1sh, nullptr, h1, N_NODES, F1, FXD, F1, 0);
    gat_aggr_k<<<((size_t)N_NODES * HEADS1 * 32 + T - 1) / T, T, 0, st>>>(
        off, csrc, as, ad, h1, b1, acc1, HEADS1);

    // --- GATConv2 (H=1, D=128) + fused max pool ---
    gemm(st, acc1, W2sh, nullptr, h2, N_NODES, DCH, F1, DCH, 0);
    alpha_k<<<(N_NODES + T - 1) / T, T, 0, st>>>(h2, a_s2, a_d2, as, ad, N_NODES, 1);
    fill4_k<<<(N_GRAPH * DCH / 4 + T - 1) / T, T, 0, st>>>((float4*)pool, -INFINITY,
                                                           N_GRAPH * DCH / 4);
    gat_aggr_pool_k<<<((size_t)N_NODES * 32 + T - 1) / T, T, 0, st>>>(
        off, csrc, as, ad, h2, b2, batch, pool);
    gemm(st, pool, Wgsh, bg, vout, N_GRAPH, DCH, DCH, 512, 1);
}

extern "C" void kernel_launch(void* const* d_in, const int* in_sizes, int n_in,
                              void* d_out, int out_size)
{
    const float* x1   = (const float*)d_in[0];
    const int*   ei1  = (const int*)  d_in[1];
    const int*   bt1  = (const int*)  d_in[2];
    const float* x2   = (const float*)d_in[3];
    const int*   ei2  = (const int*)  d_in[4];
    const int*   bt2  = (const int*)  d_in[5];
    const float* cell = (const float*)d_in[6];
    const float* W1   = (const float*)d_in[7];
    const float* aS1  = (const float*)d_in[8];
    const float* aD1  = (const float*)d_in[9];
    const float* b1   = (const float*)d_in[10];
    const float* W2   = (const float*)d_in[11];
    const float* aS2  = (const float*)d_in[12];
    const float* aD2  = (const float*)d_in[13];
    const float* b2   = (const float*)d_in[14];
    const float* Wg   = (const float*)d_in[15];
    const float* bg   = (const float*)d_in[16];
    const float* Wr1  = (const float*)d_in[17];
    const float* br1  = (const float*)d_in[18];
    const float* Wr2  = (const float*)d_in[19];
    const float* br2  = (const float*)d_in[20];
    const float* Wr3  = (const float*)d_in[21];
    const float* br3  = (const float*)d_in[22];
    const float* Wf1  = (const float*)d_in[23];
    const float* bf1  = (const float*)d_in[24];
    const float* Wf2  = (const float*)d_in[25];
    const float* bf2  = (const float*)d_in[26];
    const float* Wf3  = (const float*)d_in[27];
    const float* bf3  = (const float*)d_in[28];
    const float* Wo   = (const float*)d_in[29];
    const float* bo   = (const float*)d_in[30];
    float* out = (float*)d_out;

    float *h1, *acc1, *h2, *as, *ad, *pool;
    float *h1B, *acc1B, *h2B, *asB, *adB, *poolB;
    float *cn, *c1, *c2, *xc, *f1, *f2, *f3, *Was, *Wad;
    int *deg, *cur, *off, *csrc, *degB, *curB, *offB, *csrcB;
    uint32_t* wsh;
    cudaGetSymbolAddress((void**)&h1,    g_h1);
    cudaGetSymbolAddress((void**)&acc1,  g_acc1);
    cudaGetSymbolAddress((void**)&h2,    g_h2);
    cudaGetSymbolAddress((void**)&as,    g_as);
    cudaGetSymbolAddress((void**)&ad,    g_ad);
    cudaGetSymbolAddress((void**)&deg,   g_deg);
    cudaGetSymbolAddress((void**)&cur,   g_cur);
    cudaGetSymbolAddress((void**)&off,   g_off);
    cudaGetSymbolAddress((void**)&csrc,  g_csrc);
    cudaGetSymbolAddress((void**)&pool,  g_pool);
    cudaGetSymbolAddress((void**)&h1B,   g_h1B);
    cudaGetSymbolAddress((void**)&acc1B, g_acc1B);
    cudaGetSymbolAddress((void**)&h2B,   g_h2B);
    cudaGetSymbolAddress((void**)&asB,   g_asB);
    cudaGetSymbolAddress((void**)&adB,   g_adB);
    cudaGetSymbolAddress((void**)&degB,  g_degB);
    cudaGetSymbolAddress((void**)&curB,  g_curB);
    cudaGetSymbolAddress((void**)&offB,  g_offB);
    cudaGetSymbolAddress((void**)&csrcB, g_csrcB);
    cudaGetSymbolAddress((void**)&poolB, g_poolB);
    cudaGetSymbolAddress((void**)&cn,    g_cn);
    cudaGetSymbolAddress((void**)&c1,    g_c1);
    cudaGetSymbolAddress((void**)&c2,    g_c2);
    cudaGetSymbolAddress((void**)&xc,    g_xc);
    cudaGetSymbolAddress((void**)&f1,    g_f1);
    cudaGetSymbolAddress((void**)&f2,    g_f2);
    cudaGetSymbolAddress((void**)&f3,    g_f3);
    cudaGetSymbolAddress((void**)&Was,   g_Was);
    cudaGetSymbolAddress((void**)&Wad,   g_Wad);
    cudaGetSymbolAddress((void**)&wsh,   g_wsh);

    cudaStream_t s2, s3;
    cudaStreamCreateWithFlags(&s2, cudaStreamNonBlocking);
    cudaStreamCreateWithFlags(&s3, cudaStreamNonBlocking);
    cudaEvent_t e0, e2, e3;
    cudaEventCreateWithFlags(&e0, cudaEventDisableTiming);
    cudaEventCreateWithFlags(&e2, cudaEventDisableTiming);
    cudaEventCreateWithFlags(&e3, cudaEventDisableTiming);

    // prologue on stream 0: branch weights shuffle + attention projection
    shuf(0, W1, wsh + SH_W1, FXD, F1);
    shuf(0, W2, wsh + SH_W2, F1, DCH);
    shuf(0, Wg, wsh + SH_WG, DCH, DCH);
    proj_att_k<<<(FXD * HEADS1 + 255) / 256, 256>>>(W1, aS1, aD1, Was, Wad);

    cudaEventRecord(e0, 0);
    cudaStreamWaitEvent(s2, e0, 0);
    cudaStreamWaitEvent(s3, e0, 0);

    // cell-branch weights shuffle on s3 (only used there / after its join)
    shuf(s3, Wr1, wsh + SH_WR1, FXT, 2048);
    shuf(s3, Wr2, wsh + SH_WR2, 2048, 512);
    shuf(s3, Wr3, wsh + SH_WR3, 512, 256);
    shuf(s3, Wf1, wsh + SH_WF1, 512, 1024);
    shuf(s3, Wf2, wsh + SH_WF2, 1024, 512);
    shuf(s3, Wf3, wsh + SH_WF3, 512, 128);
    shuf(s3, Wo,  wsh + SH_WO,  128, 2);

    // branch 1 -> xc[:, 0:128)
    run_branch(0,  x1, ei1, bt1, wsh + SH_W1, Was, Wad, b1,
               wsh + SH_W2, aS2, aD2, b2, wsh + SH_WG, bg,
               h1, acc1, h2, as, ad, deg, cur, off, csrc, pool, xc);
    // branch 2 -> xc[:, 128:256)
    run_branch(s2, x2, ei2, bt2, wsh + SH_W1, Was, Wad, b1,
               wsh + SH_W2, aS2, aD2, b2, wsh + SH_WG, bg,
               h1B, acc1B, h2B, asB, adB, degB, curB, offB, csrcB, poolB, xc + 128);
    // cell branch -> xc[:, 256:512)
    l2norm_k<<<N_GRAPH, 256, 0, s3>>>(cell, cn, FXT);
    gemm(s3, cn, wsh + SH_WR1, br1, c1, N_GRAPH, 2048, FXT, 2048, 1);
    gemm(s3, c1, wsh + SH_WR2, br2, c2, N_GRAPH, 512, 2048, 512, 1);
    gemm(s3, c2, wsh + SH_WR3, br3, xc + 256, N_GRAPH, 256, 512, 512, 1);

    // join
    cudaEventRecord(e2, s2);
    cudaEventRecord(e3, s3);
    cudaStreamWaitEvent(0, e2, 0);
    cudaStreamWaitEvent(0, e3, 0);

    // fuse head (launch stream)
    l2norm_k<<<N_GRAPH, 256>>>(xc, xc, 512);
    gemm(0, xc, wsh + SH_WF1, bf1, f1, N_GRAPH, 1024, 512, 1024, 1);
    gemm(0, f1, wsh + SH_WF2, bf2, f2, N_GRAPH, 512, 1024, 512, 1);
    gemm(0, f2, wsh + SH_WF3, bf3, f3, N_GRAPH, 128, 512, 128, 1);
    gemm(0, f3, wsh + SH_WO, bo, out, N_GRAPH, 2, 128, 2, 0);

    cudaEventDestroy(e0); cudaEventDestroy(e2); cudaEventDestroy(e3);
    cudaStreamDestroy(s2); cudaStreamDestroy(s3);
}